// round 10
// baseline (speedup 1.0000x reference)
#include <cuda_runtime.h>
#include <math.h>

#define Bn 8
#define Hh 640
#define Ww 640
#define HW (Hh*Ww)          // 409600
#define HW4 (HW/4)          // 102400
#define NCH 10
#define NKER 5
#define NL 16
#define NEGINF (-1e30f)

// ---------------- scratch ----------------
struct Scal {
    int   negcount[Bn];
    int   npos[Bn];
    float posSum[Bn], posSum2[Bn], totNegQ[Bn], negselSum[Bn], lvSum[Bn];
    float kInter[Bn*NKER], kU1[Bn*NKER], kU2[Bn*NKER];
    float embCnt[Bn][NL];
    float embSum[Bn][NL][4];
};
__device__ Scal gS;
__device__ unsigned g_negbits[Bn*HW];

__device__ __forceinline__ float sigm(float x){ return 1.0f/(1.0f+expf(-x)); }

// ------- fused dilate (sigmoid-of-max) + OHEM stats + staged compaction ----
// grid (20,20,Bn), block (32,8). Tile 32x32, halo 4.
__global__ void k_dilstats(const float* __restrict__ pred,
                           const float* __restrict__ gt,
                           const float* __restrict__ tm){
    __shared__ float sIn[40][41];
    __shared__ float sHm[40][33];
    __shared__ unsigned sNeg[1024];
    __shared__ int sCnt, sBase;
    __shared__ float sR0[8], sR1[8], sR2[8], sR3[8];
    int b = blockIdx.z;
    int gx0 = blockIdx.x*32 - 4, gy0 = blockIdx.y*32 - 4;
    int tid = threadIdx.y*32 + threadIdx.x;
    int lane = tid & 31, wid = tid >> 5;
    const float* p0 = pred + b*NCH*HW;

    if (tid == 0) sCnt = 0;
    for (int idx = tid; idx < 1600; idx += 256){
        int r = idx/40, c = idx - 40*r;
        int gy = gy0 + r, gx = gx0 + c;
        sIn[r][c] = (gy>=0 && gy<Hh && gx>=0 && gx<Ww) ? p0[gy*Ww + gx] : NEGINF;
    }
    __syncthreads();
    for (int idx = tid; idx < 1280; idx += 256){
        int r = idx >> 5, c = idx & 31;
        float m = sIn[r][c];
        #pragma unroll
        for (int j=1;j<9;j++) m = fmaxf(m, sIn[r][c+j]);
        sHm[r][c] = m;
    }
    __syncthreads();

    int pc = 0; float ps = 0.f, ps2 = 0.f, qn = 0.f;
    #pragma unroll
    for (int k=0;k<4;k++){
        int r = threadIdx.y*4 + k;
        int c = threadIdx.x;
        float m = sHm[r][c];
        #pragma unroll
        for (int j=1;j<9;j++) m = fmaxf(m, sHm[r+j][c]);
        float v = sigm(m);                  // sigmoid after max (monotone)
        int gy = gy0 + 4 + r, gx = gx0 + 4 + c;
        int gi = b*HW + gy*Ww + gx;
        float g  = gt[gi];
        float mm = tm[gi];
        bool isPos = (g > 0.5f) && (mm > 0.5f);
        bool isNeg = (g <= 0.5f) && (mm > 0.5f);
        if (isPos){ pc++; ps += v; ps2 += v*v; }
        if (isNeg) qn += v*v;
        unsigned ball = __ballot_sync(0xffffffffu, isNeg);
        if (isNeg){
            int rank = __popc(ball & ((1u<<lane)-1u));
            int leader = __ffs(ball)-1;
            int base = 0;
            if (lane == leader) base = atomicAdd(&sCnt, __popc(ball));
            base = __shfl_sync(ball, base, leader);
            sNeg[base + rank] = __float_as_uint(v);
        }
    }
    #pragma unroll
    for (int o=16;o;o>>=1){
        pc  += __shfl_down_sync(0xffffffffu, pc, o);
        ps  += __shfl_down_sync(0xffffffffu, ps, o);
        ps2 += __shfl_down_sync(0xffffffffu, ps2, o);
        qn  += __shfl_down_sync(0xffffffffu, qn, o);
    }
    if (lane == 0){ sR0[wid]=(float)pc; sR1[wid]=ps; sR2[wid]=ps2; sR3[wid]=qn; }
    __syncthreads();        // covers sNeg, sCnt, sR*
    if (tid == 0){
        float a=0,bb=0,cc=0,dd=0;
        #pragma unroll
        for (int w=0;w<8;w++){ a+=sR0[w]; bb+=sR1[w]; cc+=sR2[w]; dd+=sR3[w]; }
        if (a  != 0.f) atomicAdd(&gS.npos[b], (int)a);
        if (bb != 0.f) atomicAdd(&gS.posSum[b], bb);
        if (cc != 0.f) atomicAdd(&gS.posSum2[b], cc);
        if (dd != 0.f) atomicAdd(&gS.totNegQ[b], dd);
        sBase = atomicAdd(&gS.negcount[b], sCnt);
    }
    __syncthreads();
    int cnt = sCnt, base = sBase;
    unsigned* dst = g_negbits + b*HW + base;
    for (int i = tid; i < cnt; i += 256) dst[i] = sNeg[i];
}

// ---------- radix select fallback (null launch when k >= cnt) --------------
// grid Bn x 1024
__global__ void k_selectAll(){
    __shared__ unsigned hC[4096];
    __shared__ float    hQ[4096];
    __shared__ unsigned scC[1024];
    __shared__ float    scQ[1024];
    __shared__ unsigned sPrefix;
    __shared__ int      sK;
    __shared__ float    sNegsel;
    int b = blockIdx.x;
    int t = threadIdx.x;
    int cnt = gS.negcount[b];
    int k0 = 3*gS.npos[b]; if (k0 > cnt) k0 = cnt;
    if (k0 >= cnt){
        if (t == 0) gS.negselSum[b] = gS.totNegQ[b];
        return;
    }
    if (k0 <= 0){
        if (t == 0) gS.negselSum[b] = 0.f;
        return;
    }
    if (t == 0){ sK = k0; sNegsel = 0.f; sPrefix = 0u; }
    __syncthreads();
    const unsigned* nb = g_negbits + b*HW;
    for (int level = 1; level <= 3; level++){
        int K = sK;
        unsigned pfx = sPrefix;
        for (int i=t;i<4096;i+=1024){ hC[i]=0u; hQ[i]=0.f; }
        __syncthreads();
        for (int j = t; j - t < cnt; j += 1024){
            bool in = j < cnt;
            unsigned bits = in ? nb[j] : 0u;
            unsigned bin = 0; bool ok = false;
            if (in){
                if (level == 1){ bin = bits >> 20; ok = true; }
                else if (level == 2){ ok = (bits>>20)==(pfx>>20); bin = (bits>>8)&0xFFFu; }
                else { ok = (bits>>8)==(pfx>>8); bin = bits & 0xFFu; }
            }
            float v = __uint_as_float(bits);
            float q = v*v;
            unsigned key = ok ? bin : 0xFFFFFFFFu;
            unsigned grp = __match_any_sync(0xffffffffu, key);
            if (grp == 0xffffffffu){
                if (ok){
                    #pragma unroll
                    for (int o=16;o;o>>=1) q += __shfl_down_sync(0xffffffffu, q, o);
                    if ((t & 31) == 0){ atomicAdd(&hC[bin], 32u); atomicAdd(&hQ[bin], q); }
                }
            } else if (ok){
                atomicAdd(&hC[bin], 1u); atomicAdd(&hQ[bin], q);
            }
        }
        __syncthreads();
        int nbins = (level == 3) ? 256 : 4096;
        int per = (nbins >= 1024) ? (nbins >> 10) : 1;
        int hi = nbins - 1 - t*per;
        unsigned c = 0; float q = 0.f;
        if (hi >= 0){
            for (int i=0;i<per;i++){ int bx = hi - i; if (bx >= 0){ c += hC[bx]; q += hQ[bx]; } }
        }
        scC[t] = c; scQ[t] = q;
        __syncthreads();
        for (int off=1; off<1024; off<<=1){
            unsigned cv = (t >= off) ? scC[t-off] : 0u;
            float    qv = (t >= off) ? scQ[t-off] : 0.f;
            __syncthreads();
            scC[t] += cv; scQ[t] += qv;
            __syncthreads();
        }
        unsigned incl = scC[t], excl = incl - c;
        if (hi >= 0 && (int)excl < K && K <= (int)incl){
            unsigned acc = excl;
            float qacc = scQ[t] - q;
            int chosen = hi;
            for (int i=0;i<per;i++){
                int bx = hi - i;
                unsigned cc = hC[bx];
                if (acc + cc >= (unsigned)K){ chosen = bx; break; }
                acc += cc; qacc += hQ[bx];
            }
            sK = K - (int)acc;
            sNegsel += qacc;
            if (level == 1)      sPrefix = ((unsigned)chosen) << 20;
            else if (level == 2) sPrefix |= ((unsigned)chosen) << 8;
            else                 sPrefix |= (unsigned)chosen;
        }
        __syncthreads();
    }
    if (t == 0){
        float tv = __uint_as_float(sPrefix);
        gS.negselSum[b] = sNegsel + (float)sK * tv * tv;
    }
}

// ---------------- kernels dice: flat grid, 1 quad/thread -------------------
// grid 3200 x 256
__global__ void k_kern(const float* __restrict__ pred,
                       const float* __restrict__ gtk,
                       const float* __restrict__ tm){
    __shared__ float sRed[8][15];
    int b = blockIdx.x / 400;
    int i = (blockIdx.x - b*400)*256 + threadIdx.x;
    float4 m = ((const float4*)(tm + b*HW))[i];
    const float* pb = pred + (b*NCH + 1)*HW;
    const float* gb = gtk  + b*NKER*HW;
    float si[5], s1[5], s2[5];
    #pragma unroll
    for (int kc=0;kc<5;kc++){
        float4 p = ((const float4*)(pb + kc*HW))[i];
        float4 g = ((const float4*)(gb + kc*HW))[i];
        float a=0.f,u=0.f,c=0.f;
        if (m.x > 0.5f){ float pp = sigm(p.x); a+=pp*g.x; u+=pp*pp; c+=g.x; }
        if (m.y > 0.5f){ float pp = sigm(p.y); a+=pp*g.y; u+=pp*pp; c+=g.y; }
        if (m.z > 0.5f){ float pp = sigm(p.z); a+=pp*g.z; u+=pp*pp; c+=g.z; }
        if (m.w > 0.5f){ float pp = sigm(p.w); a+=pp*g.w; u+=pp*pp; c+=g.w; }
        si[kc]=a; s1[kc]=u; s2[kc]=c;
    }
    int lane = threadIdx.x & 31, wid = threadIdx.x >> 5;
    #pragma unroll
    for (int kc=0;kc<5;kc++){
        float a = si[kc], u = s1[kc], c = s2[kc];
        #pragma unroll
        for (int o=16;o;o>>=1){
            a += __shfl_down_sync(0xffffffffu, a, o);
            u += __shfl_down_sync(0xffffffffu, u, o);
            c += __shfl_down_sync(0xffffffffu, c, o);
        }
        if (lane == 0){ sRed[wid][kc*3]=a; sRed[wid][kc*3+1]=u; sRed[wid][kc*3+2]=c; }
    }
    __syncthreads();
    if (threadIdx.x < 15){
        float s = 0.f;
        #pragma unroll
        for (int w=0;w<8;w++) s += sRed[w][threadIdx.x];
        int kc = threadIdx.x/3, comp = threadIdx.x - 3*kc;
        if (s != 0.f){
            if (comp==0) atomicAdd(&gS.kInter[b*NKER+kc], s);
            else if (comp==1) atomicAdd(&gS.kU1[b*NKER+kc], s);
            else atomicAdd(&gS.kU2[b*NKER+kc], s);
        }
    }
}

// ------- emb pass 1: REGISTER accumulators + predicated adds ---------------
// grid (32, Bn) x 256 ; no smem tables, no RMW latency chains
__global__ void __launch_bounds__(256) k_emb1(const float* __restrict__ pred,
                       const int* __restrict__ inst,
                       const float* __restrict__ tm){
    __shared__ float sS[8][80];
    int b = blockIdx.y;
    int t = threadIdx.x;
    int lane = t & 31, wid = t >> 5;
    float cnt[NL], a0[NL], a1[NL], a2[NL], a3[NL];
    #pragma unroll
    for (int l=0;l<NL;l++){ cnt[l]=0.f; a0[l]=0.f; a1[l]=0.f; a2[l]=0.f; a3[l]=0.f; }

    const float4* tm4 = (const float4*)(tm + b*HW);
    const int4*   in4 = (const int4*)(inst + b*HW);
    const float4* e0 = (const float4*)(pred + (b*NCH + 6)*HW);
    const float4* e1 = (const float4*)(pred + (b*NCH + 7)*HW);
    const float4* e2 = (const float4*)(pred + (b*NCH + 8)*HW);
    const float4* e3 = (const float4*)(pred + (b*NCH + 9)*HW);
    int stride = gridDim.x*blockDim.x;
    for (int i = blockIdx.x*blockDim.x + t; i < HW4; i += stride){
        float4 m = tm4[i]; int4 gi = in4[i];
        float4 va = e0[i], vb = e1[i], vc = e2[i], vd = e3[i];
        float mv[4] = {m.x, m.y, m.z, m.w};
        int   lv[4] = {gi.x & 15, gi.y & 15, gi.z & 15, gi.w & 15};
        float av[4] = {va.x, va.y, va.z, va.w};
        float bv[4] = {vb.x, vb.y, vb.z, vb.w};
        float cv[4] = {vc.x, vc.y, vc.z, vc.w};
        float dv[4] = {vd.x, vd.y, vd.z, vd.w};
        #pragma unroll
        for (int comp=0; comp<4; comp++){
            bool on = mv[comp] > 0.5f;
            int lab = lv[comp];
            #pragma unroll
            for (int l=0;l<NL;l++){
                bool hit = on && (lab == l);
                if (hit){
                    cnt[l] += 1.f;
                    a0[l] += av[comp];
                    a1[l] += bv[comp];
                    a2[l] += cv[comp];
                    a3[l] += dv[comp];
                }
            }
        }
    }
    // warp reduce 80 accumulators, stage per warp, cross-warp sum, atomics
    #pragma unroll
    for (int l=0;l<NL;l++){
        float v0=cnt[l], v1=a0[l], v2=a1[l], v3=a2[l], v4=a3[l];
        #pragma unroll
        for (int o=16;o;o>>=1){
            v0 += __shfl_down_sync(0xffffffffu, v0, o);
            v1 += __shfl_down_sync(0xffffffffu, v1, o);
            v2 += __shfl_down_sync(0xffffffffu, v2, o);
            v3 += __shfl_down_sync(0xffffffffu, v3, o);
            v4 += __shfl_down_sync(0xffffffffu, v4, o);
        }
        if (lane == 0){
            sS[wid][l*5+0]=v0; sS[wid][l*5+1]=v1; sS[wid][l*5+2]=v2;
            sS[wid][l*5+3]=v3; sS[wid][l*5+4]=v4;
        }
    }
    __syncthreads();
    if (t < 80){
        float s = 0.f;
        #pragma unroll
        for (int w=0;w<8;w++) s += sS[w][t];
        if (s != 0.f){
            int l = t/5, comp = t - 5*l;
            if (comp == 0) atomicAdd(&gS.embCnt[b][l], s);
            else           atomicAdd(&gS.embSum[b][l][comp-1], s);
        }
    }
}

// ---------------- emb pass 2: hinge variance, flat grid, 1 quad/thread -----
// grid 3200 x 256
__global__ void k_emb2(const float* __restrict__ pred,
                       const int* __restrict__ inst,
                       const float* __restrict__ tm){
    __shared__ float sM[NL][4];
    __shared__ float sInv[NL];
    __shared__ float sRed[8];
    int b = blockIdx.x / 400;
    int i = (blockIdx.x - b*400)*256 + threadIdx.x;
    if (threadIdx.x < NL){
        int l = threadIdx.x;
        float c = gS.embCnt[b][l];
        float inv = 1.f / fmaxf(c, 1.f);
        sInv[l] = inv;
        #pragma unroll
        for (int d=0;d<4;d++) sM[l][d] = gS.embSum[b][l][d]*inv;
    }
    __syncthreads();
    float4 m = ((const float4*)(tm + b*HW))[i];
    int4 gi  = ((const int4*)(inst + b*HW))[i];
    float4 a = ((const float4*)(pred + (b*NCH + 6)*HW))[i];
    float4 bb= ((const float4*)(pred + (b*NCH + 7)*HW))[i];
    float4 c = ((const float4*)(pred + (b*NCH + 8)*HW))[i];
    float4 d = ((const float4*)(pred + (b*NCH + 9)*HW))[i];
    float acc = 0.f;
    float mv[4] = {m.x, m.y, m.z, m.w};
    int   lv[4] = {gi.x & 15, gi.y & 15, gi.z & 15, gi.w & 15};
    float av[4] = {a.x, a.y, a.z, a.w};
    float bv[4] = {bb.x, bb.y, bb.z, bb.w};
    float cv[4] = {c.x, c.y, c.z, c.w};
    float dv[4] = {d.x, d.y, d.z, d.w};
    #pragma unroll
    for (int comp=0; comp<4; comp++){
        if (mv[comp] > 0.5f){
            int l = lv[comp];
            float v0 = av[comp] - sM[l][0];
            float v1 = bv[comp] - sM[l][1];
            float v2 = cv[comp] - sM[l][2];
            float v3 = dv[comp] - sM[l][3];
            float dd = sqrtf(v0*v0+v1*v1+v2*v2+v3*v3 + 1e-12f);
            float h = dd - 0.5f;
            if (h > 0.f) acc += h*h*sInv[l];
        }
    }
    int lane = threadIdx.x & 31, wid = threadIdx.x >> 5;
    #pragma unroll
    for (int o=16;o;o>>=1) acc += __shfl_down_sync(0xffffffffu, acc, o);
    if (lane == 0) sRed[wid] = acc;
    __syncthreads();
    if (threadIdx.x == 0){
        float s = 0.f;
        #pragma unroll
        for (int w=0;w<8;w++) s += sRed[w];
        if (s != 0.f) atomicAdd(&gS.lvSum[b], s);
    }
}

// ---------------- final assembly -------------------------------------------
__global__ void k_final(float* out){
    if (threadIdx.x != 0 || blockIdx.x != 0) return;
    float loss_text = 0.f;
    for (int b=0;b<Bn;b++){
        float inter = gS.posSum[b];
        float uni = gS.posSum2[b] + gS.negselSum[b] + (float)gS.npos[b] + 1e-6f;
        loss_text += 1.f - 2.f*inter/uni;
    }
    loss_text /= (float)Bn;
    float loss_k = 0.f;
    for (int r=0;r<Bn*NKER;r++){
        float uni = gS.kU1[r] + gS.kU2[r] + 1e-6f;
        loss_k += 1.f - 2.f*gS.kInter[r]/uni;
    }
    loss_k /= (float)(Bn*NKER);
    float lvT=0.f, ldT=0.f, lrT=0.f;
    for (int b=0;b<Bn;b++){
        int n=0;
        bool pres[NL];
        float mean[NL][4];
        for (int l=0;l<NL;l++){
            float cc = gS.embCnt[b][l];
            pres[l] = cc > 0.f;
            if (pres[l]) n++;
            float inv = 1.f/fmaxf(cc,1.f);
            for (int d=0;d<4;d++) mean[l][d] = gS.embSum[b][l][d]*inv;
        }
        float nf = (float)n;
        float lv = gS.lvSum[b] / fmaxf(nf, 1.f);
        float ld = 0.f;
        for (int ii=0;ii<NL;ii++) for (int j=ii+1;j<NL;j++){
            if (pres[ii] && pres[j]){
                float d2=0.f;
                for (int d=0;d<4;d++){
                    float df = mean[ii][d]-mean[j][d];
                    d2 += df*df;
                }
                float pd = sqrtf(d2 + 1e-12f);
                float h = fmaxf(3.0f - pd, 0.f);
                ld += h*h;
            }
        }
        ld /= fmaxf(nf*(nf-1.f), 1.f);
        float lr = 0.f;
        for (int l=0;l<NL;l++){
            if (pres[l]){
                float d2=0.f;
                for (int d=0;d<4;d++) d2 += mean[l][d]*mean[l][d];
                lr += sqrtf(d2 + 1e-12f);
            }
        }
        lr /= fmaxf(nf, 1.f);
        float act = (n > 1) ? 1.f : 0.f;
        lvT += act*lv; ldT += act*ld; lrT += act*lr;
    }
    float loss_emb = 0.25f*(lvT + ldT + 0.001f*(lrT/(float)Bn));
    float loss = loss_k + 0.5f*loss_text + loss_emb;
    out[0]=loss; out[1]=loss_text; out[2]=loss_k; out[3]=loss_emb;
}

// ---- launch: 3 overlapped chains; ncu (workload 5) lands on k_emb1 --------
extern "C" void kernel_launch(void* const* d_in, const int* in_sizes, int n_in,
                              void* d_out, int out_size){
    const float* pred   = (const float*)d_in[0];
    const float* gtText = (const float*)d_in[1];
    const float* gtk    = (const float*)d_in[2];
    const float* tm     = (const float*)d_in[3];
    const int*   inst   = (const int*)d_in[4];
    float* out = (float*)d_out;

    static cudaStream_t s1 = nullptr, s2 = nullptr;
    static cudaEvent_t ev0 = nullptr, ev1 = nullptr, ev2 = nullptr;
    static void* pS = nullptr;
    if (s1 == nullptr){
        cudaStreamCreateWithFlags(&s1, cudaStreamNonBlocking);
        cudaStreamCreateWithFlags(&s2, cudaStreamNonBlocking);
        cudaEventCreateWithFlags(&ev0, cudaEventDisableTiming);
        cudaEventCreateWithFlags(&ev1, cudaEventDisableTiming);
        cudaEventCreateWithFlags(&ev2, cudaEventDisableTiming);
        cudaGetSymbolAddress(&pS, gS);
    }

    cudaMemsetAsync(pS, 0, sizeof(Scal), 0);            // workload 1
    cudaEventRecord(ev0, 0);

    // chain C (main): kern                              // workload 2
    k_kern<<<3200, 256>>>(pred, gtk, tm);

    // chain B (s1): dilstats -> select                  // workloads 3,4
    cudaStreamWaitEvent(s1, ev0, 0);
    k_dilstats<<<dim3(20,20,Bn), dim3(32,8), 0, s1>>>(pred, gtText, tm);
    k_selectAll<<<Bn, 1024, 0, s1>>>();
    cudaEventRecord(ev1, s1);

    // chain A (s2): emb1 -> emb2                        // workloads 5,6
    cudaStreamWaitEvent(s2, ev0, 0);
    k_emb1<<<dim3(32, Bn), 256, 0, s2>>>(pred, inst, tm);
    k_emb2<<<3200, 256, 0, s2>>>(pred, inst, tm);
    cudaEventRecord(ev2, s2);

    // join
    cudaStreamWaitEvent(0, ev1, 0);
    cudaStreamWaitEvent(0, ev2, 0);
    k_final<<<1, 32>>>(out);                             // workload 7
}

// round 11
// speedup vs baseline: 1.4093x; 1.4093x over previous
#include <cuda_runtime.h>
#include <math.h>

#define Bn 8
#define Hh 640
#define Ww 640
#define HW (Hh*Ww)          // 409600
#define HW4 (HW/4)          // 102400
#define NCH 10
#define NKER 5
#define NL 16
#define NEGINF (-1e30f)

// ---------------- scratch ----------------
struct Scal {
    int   negcount[Bn];
    int   npos[Bn];
    float posSum[Bn], posSum2[Bn], totNegQ[Bn], negselSum[Bn], lvSum[Bn];
    float kInter[Bn*NKER], kU1[Bn*NKER], kU2[Bn*NKER];
    float embCnt[Bn][NL];
    float embSum[Bn][NL][4];
};
__device__ Scal gS;
__device__ unsigned g_negbits[Bn*HW];

__device__ __forceinline__ float sigm(float x){ return 1.0f/(1.0f+expf(-x)); }

// ------- fused dilate (sigmoid-of-max) + OHEM stats + staged compaction ----
// grid (20,20,Bn), block (32,8). Tile 32x32, halo 4.
__global__ void k_dilstats(const float* __restrict__ pred,
                           const float* __restrict__ gt,
                           const float* __restrict__ tm){
    __shared__ float sIn[40][41];
    __shared__ float sHm[40][33];
    __shared__ unsigned sNeg[1024];
    __shared__ int sCnt, sBase;
    __shared__ float sR0[8], sR1[8], sR2[8], sR3[8];
    int b = blockIdx.z;
    int gx0 = blockIdx.x*32 - 4, gy0 = blockIdx.y*32 - 4;
    int tid = threadIdx.y*32 + threadIdx.x;
    int lane = tid & 31, wid = tid >> 5;
    const float* p0 = pred + b*NCH*HW;

    if (tid == 0) sCnt = 0;
    for (int idx = tid; idx < 1600; idx += 256){
        int r = idx/40, c = idx - 40*r;
        int gy = gy0 + r, gx = gx0 + c;
        sIn[r][c] = (gy>=0 && gy<Hh && gx>=0 && gx<Ww) ? p0[gy*Ww + gx] : NEGINF;
    }
    __syncthreads();
    for (int idx = tid; idx < 1280; idx += 256){
        int r = idx >> 5, c = idx & 31;
        float m = sIn[r][c];
        #pragma unroll
        for (int j=1;j<9;j++) m = fmaxf(m, sIn[r][c+j]);
        sHm[r][c] = m;
    }
    __syncthreads();

    int pc = 0; float ps = 0.f, ps2 = 0.f, qn = 0.f;
    #pragma unroll
    for (int k=0;k<4;k++){
        int r = threadIdx.y*4 + k;
        int c = threadIdx.x;
        float m = sHm[r][c];
        #pragma unroll
        for (int j=1;j<9;j++) m = fmaxf(m, sHm[r+j][c]);
        float v = sigm(m);                  // sigmoid after max (monotone)
        int gy = gy0 + 4 + r, gx = gx0 + 4 + c;
        int gi = b*HW + gy*Ww + gx;
        float g  = gt[gi];
        float mm = tm[gi];
        bool isPos = (g > 0.5f) && (mm > 0.5f);
        bool isNeg = (g <= 0.5f) && (mm > 0.5f);
        if (isPos){ pc++; ps += v; ps2 += v*v; }
        if (isNeg) qn += v*v;
        unsigned ball = __ballot_sync(0xffffffffu, isNeg);
        if (isNeg){
            int rank = __popc(ball & ((1u<<lane)-1u));
            int leader = __ffs(ball)-1;
            int base = 0;
            if (lane == leader) base = atomicAdd(&sCnt, __popc(ball));
            base = __shfl_sync(ball, base, leader);
            sNeg[base + rank] = __float_as_uint(v);
        }
    }
    #pragma unroll
    for (int o=16;o;o>>=1){
        pc  += __shfl_down_sync(0xffffffffu, pc, o);
        ps  += __shfl_down_sync(0xffffffffu, ps, o);
        ps2 += __shfl_down_sync(0xffffffffu, ps2, o);
        qn  += __shfl_down_sync(0xffffffffu, qn, o);
    }
    if (lane == 0){ sR0[wid]=(float)pc; sR1[wid]=ps; sR2[wid]=ps2; sR3[wid]=qn; }
    __syncthreads();        // covers sNeg, sCnt, sR*
    if (tid == 0){
        float a=0,bb=0,cc=0,dd=0;
        #pragma unroll
        for (int w=0;w<8;w++){ a+=sR0[w]; bb+=sR1[w]; cc+=sR2[w]; dd+=sR3[w]; }
        if (a  != 0.f) atomicAdd(&gS.npos[b], (int)a);
        if (bb != 0.f) atomicAdd(&gS.posSum[b], bb);
        if (cc != 0.f) atomicAdd(&gS.posSum2[b], cc);
        if (dd != 0.f) atomicAdd(&gS.totNegQ[b], dd);
        sBase = atomicAdd(&gS.negcount[b], sCnt);
    }
    __syncthreads();
    int cnt = sCnt, base = sBase;
    unsigned* dst = g_negbits + b*HW + base;
    for (int i = tid; i < cnt; i += 256) dst[i] = sNeg[i];
}

// ---------- radix select fallback (null launch when k >= cnt) --------------
// grid Bn x 1024
__global__ void k_selectAll(){
    __shared__ unsigned hC[4096];
    __shared__ float    hQ[4096];
    __shared__ unsigned scC[1024];
    __shared__ float    scQ[1024];
    __shared__ unsigned sPrefix;
    __shared__ int      sK;
    __shared__ float    sNegsel;
    int b = blockIdx.x;
    int t = threadIdx.x;
    int cnt = gS.negcount[b];
    int k0 = 3*gS.npos[b]; if (k0 > cnt) k0 = cnt;
    if (k0 >= cnt){
        if (t == 0) gS.negselSum[b] = gS.totNegQ[b];
        return;
    }
    if (k0 <= 0){
        if (t == 0) gS.negselSum[b] = 0.f;
        return;
    }
    if (t == 0){ sK = k0; sNegsel = 0.f; sPrefix = 0u; }
    __syncthreads();
    const unsigned* nb = g_negbits + b*HW;
    for (int level = 1; level <= 3; level++){
        int K = sK;
        unsigned pfx = sPrefix;
        for (int i=t;i<4096;i+=1024){ hC[i]=0u; hQ[i]=0.f; }
        __syncthreads();
        for (int j = t; j - t < cnt; j += 1024){
            bool in = j < cnt;
            unsigned bits = in ? nb[j] : 0u;
            unsigned bin = 0; bool ok = false;
            if (in){
                if (level == 1){ bin = bits >> 20; ok = true; }
                else if (level == 2){ ok = (bits>>20)==(pfx>>20); bin = (bits>>8)&0xFFFu; }
                else { ok = (bits>>8)==(pfx>>8); bin = bits & 0xFFu; }
            }
            float v = __uint_as_float(bits);
            float q = v*v;
            unsigned key = ok ? bin : 0xFFFFFFFFu;
            unsigned grp = __match_any_sync(0xffffffffu, key);
            if (grp == 0xffffffffu){
                if (ok){
                    #pragma unroll
                    for (int o=16;o;o>>=1) q += __shfl_down_sync(0xffffffffu, q, o);
                    if ((t & 31) == 0){ atomicAdd(&hC[bin], 32u); atomicAdd(&hQ[bin], q); }
                }
            } else if (ok){
                atomicAdd(&hC[bin], 1u); atomicAdd(&hQ[bin], q);
            }
        }
        __syncthreads();
        int nbins = (level == 3) ? 256 : 4096;
        int per = (nbins >= 1024) ? (nbins >> 10) : 1;
        int hi = nbins - 1 - t*per;
        unsigned c = 0; float q = 0.f;
        if (hi >= 0){
            for (int i=0;i<per;i++){ int bx = hi - i; if (bx >= 0){ c += hC[bx]; q += hQ[bx]; } }
        }
        scC[t] = c; scQ[t] = q;
        __syncthreads();
        for (int off=1; off<1024; off<<=1){
            unsigned cv = (t >= off) ? scC[t-off] : 0u;
            float    qv = (t >= off) ? scQ[t-off] : 0.f;
            __syncthreads();
            scC[t] += cv; scQ[t] += qv;
            __syncthreads();
        }
        unsigned incl = scC[t], excl = incl - c;
        if (hi >= 0 && (int)excl < K && K <= (int)incl){
            unsigned acc = excl;
            float qacc = scQ[t] - q;
            int chosen = hi;
            for (int i=0;i<per;i++){
                int bx = hi - i;
                unsigned cc = hC[bx];
                if (acc + cc >= (unsigned)K){ chosen = bx; break; }
                acc += cc; qacc += hQ[bx];
            }
            sK = K - (int)acc;
            sNegsel += qacc;
            if (level == 1)      sPrefix = ((unsigned)chosen) << 20;
            else if (level == 2) sPrefix |= ((unsigned)chosen) << 8;
            else                 sPrefix |= (unsigned)chosen;
        }
        __syncthreads();
    }
    if (t == 0){
        float tv = __uint_as_float(sPrefix);
        gS.negselSum[b] = sNegsel + (float)sK * tv * tv;
    }
}

// ---------------- kernels dice: flat grid, 1 quad/thread -------------------
// grid 3200 x 256
__global__ void k_kern(const float* __restrict__ pred,
                       const float* __restrict__ gtk,
                       const float* __restrict__ tm){
    __shared__ float sRed[8][15];
    int b = blockIdx.x / 400;
    int i = (blockIdx.x - b*400)*256 + threadIdx.x;
    float4 m = ((const float4*)(tm + b*HW))[i];
    const float* pb = pred + (b*NCH + 1)*HW;
    const float* gb = gtk  + b*NKER*HW;
    float si[5], s1[5], s2[5];
    #pragma unroll
    for (int kc=0;kc<5;kc++){
        float4 p = ((const float4*)(pb + kc*HW))[i];
        float4 g = ((const float4*)(gb + kc*HW))[i];
        float a=0.f,u=0.f,c=0.f;
        if (m.x > 0.5f){ float pp = sigm(p.x); a+=pp*g.x; u+=pp*pp; c+=g.x; }
        if (m.y > 0.5f){ float pp = sigm(p.y); a+=pp*g.y; u+=pp*pp; c+=g.y; }
        if (m.z > 0.5f){ float pp = sigm(p.z); a+=pp*g.z; u+=pp*pp; c+=g.z; }
        if (m.w > 0.5f){ float pp = sigm(p.w); a+=pp*g.w; u+=pp*pp; c+=g.w; }
        si[kc]=a; s1[kc]=u; s2[kc]=c;
    }
    int lane = threadIdx.x & 31, wid = threadIdx.x >> 5;
    #pragma unroll
    for (int kc=0;kc<5;kc++){
        float a = si[kc], u = s1[kc], c = s2[kc];
        #pragma unroll
        for (int o=16;o;o>>=1){
            a += __shfl_down_sync(0xffffffffu, a, o);
            u += __shfl_down_sync(0xffffffffu, u, o);
            c += __shfl_down_sync(0xffffffffu, c, o);
        }
        if (lane == 0){ sRed[wid][kc*3]=a; sRed[wid][kc*3+1]=u; sRed[wid][kc*3+2]=c; }
    }
    __syncthreads();
    if (threadIdx.x < 15){
        float s = 0.f;
        #pragma unroll
        for (int w=0;w<8;w++) s += sRed[w][threadIdx.x];
        int kc = threadIdx.x/3, comp = threadIdx.x - 3*kc;
        if (s != 0.f){
            if (comp==0) atomicAdd(&gS.kInter[b*NKER+kc], s);
            else if (comp==1) atomicAdd(&gS.kU1[b*NKER+kc], s);
            else atomicAdd(&gS.kU2[b*NKER+kc], s);
        }
    }
}

// ------- emb pass 1: REGISTER accumulators + predicated adds ---------------
// grid (32, Bn) x 256
__global__ void __launch_bounds__(256) k_emb1(const float* __restrict__ pred,
                       const int* __restrict__ inst,
                       const float* __restrict__ tm){
    __shared__ float sS[8][80];
    int b = blockIdx.y;
    int t = threadIdx.x;
    int lane = t & 31, wid = t >> 5;
    float cnt[NL], a0[NL], a1[NL], a2[NL], a3[NL];
    #pragma unroll
    for (int l=0;l<NL;l++){ cnt[l]=0.f; a0[l]=0.f; a1[l]=0.f; a2[l]=0.f; a3[l]=0.f; }

    const float4* tm4 = (const float4*)(tm + b*HW);
    const int4*   in4 = (const int4*)(inst + b*HW);
    const float4* e0 = (const float4*)(pred + (b*NCH + 6)*HW);
    const float4* e1 = (const float4*)(pred + (b*NCH + 7)*HW);
    const float4* e2 = (const float4*)(pred + (b*NCH + 8)*HW);
    const float4* e3 = (const float4*)(pred + (b*NCH + 9)*HW);
    int stride = gridDim.x*blockDim.x;
    for (int i = blockIdx.x*blockDim.x + t; i < HW4; i += stride){
        float4 m = tm4[i]; int4 gi = in4[i];
        float4 va = e0[i], vb = e1[i], vc = e2[i], vd = e3[i];
        float mv[4] = {m.x, m.y, m.z, m.w};
        int   lv[4] = {gi.x & 15, gi.y & 15, gi.z & 15, gi.w & 15};
        float av[4] = {va.x, va.y, va.z, va.w};
        float bv[4] = {vb.x, vb.y, vb.z, vb.w};
        float cv[4] = {vc.x, vc.y, vc.z, vc.w};
        float dv[4] = {vd.x, vd.y, vd.z, vd.w};
        #pragma unroll
        for (int comp=0; comp<4; comp++){
            bool on = mv[comp] > 0.5f;
            int lab = lv[comp];
            #pragma unroll
            for (int l=0;l<NL;l++){
                bool hit = on && (lab == l);
                if (hit){
                    cnt[l] += 1.f;
                    a0[l] += av[comp];
                    a1[l] += bv[comp];
                    a2[l] += cv[comp];
                    a3[l] += dv[comp];
                }
            }
        }
    }
    #pragma unroll
    for (int l=0;l<NL;l++){
        float v0=cnt[l], v1=a0[l], v2=a1[l], v3=a2[l], v4=a3[l];
        #pragma unroll
        for (int o=16;o;o>>=1){
            v0 += __shfl_down_sync(0xffffffffu, v0, o);
            v1 += __shfl_down_sync(0xffffffffu, v1, o);
            v2 += __shfl_down_sync(0xffffffffu, v2, o);
            v3 += __shfl_down_sync(0xffffffffu, v3, o);
            v4 += __shfl_down_sync(0xffffffffu, v4, o);
        }
        if (lane == 0){
            sS[wid][l*5+0]=v0; sS[wid][l*5+1]=v1; sS[wid][l*5+2]=v2;
            sS[wid][l*5+3]=v3; sS[wid][l*5+4]=v4;
        }
    }
    __syncthreads();
    if (t < 80){
        float s = 0.f;
        #pragma unroll
        for (int w=0;w<8;w++) s += sS[w][t];
        if (s != 0.f){
            int l = t/5, comp = t - 5*l;
            if (comp == 0) atomicAdd(&gS.embCnt[b][l], s);
            else           atomicAdd(&gS.embSum[b][l][comp-1], s);
        }
    }
}

// ---------------- emb pass 2: hinge variance, flat grid, 1 quad/thread -----
// grid 3200 x 256
__global__ void k_emb2(const float* __restrict__ pred,
                       const int* __restrict__ inst,
                       const float* __restrict__ tm){
    __shared__ float sM[NL][4];
    __shared__ float sInv[NL];
    __shared__ float sRed[8];
    int b = blockIdx.x / 400;
    int i = (blockIdx.x - b*400)*256 + threadIdx.x;
    if (threadIdx.x < NL){
        int l = threadIdx.x;
        float c = gS.embCnt[b][l];
        float inv = 1.f / fmaxf(c, 1.f);
        sInv[l] = inv;
        #pragma unroll
        for (int d=0;d<4;d++) sM[l][d] = gS.embSum[b][l][d]*inv;
    }
    __syncthreads();
    float4 m = ((const float4*)(tm + b*HW))[i];
    int4 gi  = ((const int4*)(inst + b*HW))[i];
    float4 a = ((const float4*)(pred + (b*NCH + 6)*HW))[i];
    float4 bb= ((const float4*)(pred + (b*NCH + 7)*HW))[i];
    float4 c = ((const float4*)(pred + (b*NCH + 8)*HW))[i];
    float4 d = ((const float4*)(pred + (b*NCH + 9)*HW))[i];
    float acc = 0.f;
    float mv[4] = {m.x, m.y, m.z, m.w};
    int   lv[4] = {gi.x & 15, gi.y & 15, gi.z & 15, gi.w & 15};
    float av[4] = {a.x, a.y, a.z, a.w};
    float bv[4] = {bb.x, bb.y, bb.z, bb.w};
    float cv[4] = {c.x, c.y, c.z, c.w};
    float dv[4] = {d.x, d.y, d.z, d.w};
    #pragma unroll
    for (int comp=0; comp<4; comp++){
        if (mv[comp] > 0.5f){
            int l = lv[comp];
            float v0 = av[comp] - sM[l][0];
            float v1 = bv[comp] - sM[l][1];
            float v2 = cv[comp] - sM[l][2];
            float v3 = dv[comp] - sM[l][3];
            float dd = sqrtf(v0*v0+v1*v1+v2*v2+v3*v3 + 1e-12f);
            float h = dd - 0.5f;
            if (h > 0.f) acc += h*h*sInv[l];
        }
    }
    int lane = threadIdx.x & 31, wid = threadIdx.x >> 5;
    #pragma unroll
    for (int o=16;o;o>>=1) acc += __shfl_down_sync(0xffffffffu, acc, o);
    if (lane == 0) sRed[wid] = acc;
    __syncthreads();
    if (threadIdx.x == 0){
        float s = 0.f;
        #pragma unroll
        for (int w=0;w<8;w++) s += sRed[w];
        if (s != 0.f) atomicAdd(&gS.lvSum[b], s);
    }
}

// ---------------- final assembly -------------------------------------------
__global__ void k_final(float* out){
    if (threadIdx.x != 0 || blockIdx.x != 0) return;
    float loss_text = 0.f;
    for (int b=0;b<Bn;b++){
        float inter = gS.posSum[b];
        float uni = gS.posSum2[b] + gS.negselSum[b] + (float)gS.npos[b] + 1e-6f;
        loss_text += 1.f - 2.f*inter/uni;
    }
    loss_text /= (float)Bn;
    float loss_k = 0.f;
    for (int r=0;r<Bn*NKER;r++){
        float uni = gS.kU1[r] + gS.kU2[r] + 1e-6f;
        loss_k += 1.f - 2.f*gS.kInter[r]/uni;
    }
    loss_k /= (float)(Bn*NKER);
    float lvT=0.f, ldT=0.f, lrT=0.f;
    for (int b=0;b<Bn;b++){
        int n=0;
        bool pres[NL];
        float mean[NL][4];
        for (int l=0;l<NL;l++){
            float cc = gS.embCnt[b][l];
            pres[l] = cc > 0.f;
            if (pres[l]) n++;
            float inv = 1.f/fmaxf(cc,1.f);
            for (int d=0;d<4;d++) mean[l][d] = gS.embSum[b][l][d]*inv;
        }
        float nf = (float)n;
        float lv = gS.lvSum[b] / fmaxf(nf, 1.f);
        float ld = 0.f;
        for (int ii=0;ii<NL;ii++) for (int j=ii+1;j<NL;j++){
            if (pres[ii] && pres[j]){
                float d2=0.f;
                for (int d=0;d<4;d++){
                    float df = mean[ii][d]-mean[j][d];
                    d2 += df*df;
                }
                float pd = sqrtf(d2 + 1e-12f);
                float h = fmaxf(3.0f - pd, 0.f);
                ld += h*h;
            }
        }
        ld /= fmaxf(nf*(nf-1.f), 1.f);
        float lr = 0.f;
        for (int l=0;l<NL;l++){
            if (pres[l]){
                float d2=0.f;
                for (int d=0;d<4;d++) d2 += mean[l][d]*mean[l][d];
                lr += sqrtf(d2 + 1e-12f);
            }
        }
        lr /= fmaxf(nf, 1.f);
        float act = (n > 1) ? 1.f : 0.f;
        lvT += act*lv; ldT += act*ld; lrT += act*lr;
    }
    float loss_emb = 0.25f*(lvT + ldT + 0.001f*(lrT/(float)Bn));
    float loss = loss_k + 0.5f*loss_text + loss_emb;
    out[0]=loss; out[1]=loss_text; out[2]=loss_k; out[3]=loss_emb;
}

// ---- launch: SERIAL (isolate emb1 rewrite from stream effects) ------------
// issue order: memset(1), dilstats(2), select(3), emb1(4), emb2(5:captured), kern(6), final(7)
extern "C" void kernel_launch(void* const* d_in, const int* in_sizes, int n_in,
                              void* d_out, int out_size){
    const float* pred   = (const float*)d_in[0];
    const float* gtText = (const float*)d_in[1];
    const float* gtk    = (const float*)d_in[2];
    const float* tm     = (const float*)d_in[3];
    const int*   inst   = (const int*)d_in[4];
    float* out = (float*)d_out;

    static void* pS = nullptr;
    if (pS == nullptr) cudaGetSymbolAddress(&pS, gS);

    cudaMemsetAsync(pS, 0, sizeof(Scal), 0);
    k_dilstats<<<dim3(20,20,Bn), dim3(32,8)>>>(pred, gtText, tm);
    k_selectAll<<<Bn, 1024>>>();
    k_emb1<<<dim3(32, Bn), 256>>>(pred, inst, tm);
    k_emb2<<<3200, 256>>>(pred, inst, tm);
    k_kern<<<3200, 256>>>(pred, gtk, tm);
    k_final<<<1, 32>>>(out);
}

// round 13
// speedup vs baseline: 1.4275x; 1.0130x over previous
#include <cuda_runtime.h>
#include <math.h>

#define Bn 8
#define Hh 640
#define Ww 640
#define HW (Hh*Ww)          // 409600
#define HW4 (HW/4)          // 102400
#define NCH 10
#define NKER 5
#define NL 16
#define NEGINF (-1e30f)

// ---------------- scratch ----------------
struct Scal {
    int   negcount[Bn];
    int   npos[Bn];
    float posSum[Bn], posSum2[Bn], totNegQ[Bn], lvSum[Bn];
    float kInter[Bn*NKER], kU1[Bn*NKER], kU2[Bn*NKER];
    float embCnt[Bn][NL];
    float embSum[Bn][NL][4];
};
__device__ Scal gS;
__device__ unsigned g_negbits[Bn*HW];

__device__ __forceinline__ float sigm(float x){ return 1.0f/(1.0f+expf(-x)); }

// ------- fused dilate (sigmoid-of-max) + OHEM stats + staged compaction ----
// grid (20,20,Bn), block (32,8). Tile 32x32, halo 4.
__global__ void k_dilstats(const float* __restrict__ pred,
                           const float* __restrict__ gt,
                           const float* __restrict__ tm){
    __shared__ float sIn[40][41];
    __shared__ float sHm[40][33];
    __shared__ unsigned sNeg[1024];
    __shared__ int sCnt, sBase;
    __shared__ float sR0[8], sR1[8], sR2[8], sR3[8];
    int b = blockIdx.z;
    int gx0 = blockIdx.x*32 - 4, gy0 = blockIdx.y*32 - 4;
    int tid = threadIdx.y*32 + threadIdx.x;
    int lane = tid & 31, wid = tid >> 5;
    const float* p0 = pred + b*NCH*HW;

    if (tid == 0) sCnt = 0;
    for (int idx = tid; idx < 1600; idx += 256){
        int r = idx/40, c = idx - 40*r;
        int gy = gy0 + r, gx = gx0 + c;
        sIn[r][c] = (gy>=0 && gy<Hh && gx>=0 && gx<Ww) ? p0[gy*Ww + gx] : NEGINF;
    }
    __syncthreads();
    for (int idx = tid; idx < 1280; idx += 256){
        int r = idx >> 5, c = idx & 31;
        float m = sIn[r][c];
        #pragma unroll
        for (int j=1;j<9;j++) m = fmaxf(m, sIn[r][c+j]);
        sHm[r][c] = m;
    }
    __syncthreads();

    int pc = 0; float ps = 0.f, ps2 = 0.f, qn = 0.f;
    #pragma unroll
    for (int k=0;k<4;k++){
        int r = threadIdx.y*4 + k;
        int c = threadIdx.x;
        float m = sHm[r][c];
        #pragma unroll
        for (int j=1;j<9;j++) m = fmaxf(m, sHm[r+j][c]);
        float v = sigm(m);                  // sigmoid after max (monotone)
        int gy = gy0 + 4 + r, gx = gx0 + 4 + c;
        int gi = b*HW + gy*Ww + gx;
        float g  = gt[gi];
        float mm = tm[gi];
        bool isPos = (g > 0.5f) && (mm > 0.5f);
        bool isNeg = (g <= 0.5f) && (mm > 0.5f);
        if (isPos){ pc++; ps += v; ps2 += v*v; }
        if (isNeg) qn += v*v;
        unsigned ball = __ballot_sync(0xffffffffu, isNeg);
        if (isNeg){
            int rank = __popc(ball & ((1u<<lane)-1u));
            int leader = __ffs(ball)-1;
            int base = 0;
            if (lane == leader) base = atomicAdd(&sCnt, __popc(ball));
            base = __shfl_sync(ball, base, leader);
            sNeg[base + rank] = __float_as_uint(v);
        }
    }
    #pragma unroll
    for (int o=16;o;o>>=1){
        pc  += __shfl_down_sync(0xffffffffu, pc, o);
        ps  += __shfl_down_sync(0xffffffffu, ps, o);
        ps2 += __shfl_down_sync(0xffffffffu, ps2, o);
        qn  += __shfl_down_sync(0xffffffffu, qn, o);
    }
    if (lane == 0){ sR0[wid]=(float)pc; sR1[wid]=ps; sR2[wid]=ps2; sR3[wid]=qn; }
    __syncthreads();        // covers sNeg, sCnt, sR*
    if (tid == 0){
        float a=0,bb=0,cc=0,dd=0;
        #pragma unroll
        for (int w=0;w<8;w++){ a+=sR0[w]; bb+=sR1[w]; cc+=sR2[w]; dd+=sR3[w]; }
        if (a  != 0.f) atomicAdd(&gS.npos[b], (int)a);
        if (bb != 0.f) atomicAdd(&gS.posSum[b], bb);
        if (cc != 0.f) atomicAdd(&gS.posSum2[b], cc);
        if (dd != 0.f) atomicAdd(&gS.totNegQ[b], dd);
        sBase = atomicAdd(&gS.negcount[b], sCnt);
    }
    __syncthreads();
    int cnt = sCnt, base = sBase;
    unsigned* dst = g_negbits + b*HW + base;
    for (int i = tid; i < cnt; i += 256) dst[i] = sNeg[i];
}

// ------- emb pass 1: REGISTER accumulators + predicated adds ---------------
// grid (32, Bn) x 256
__global__ void __launch_bounds__(256) k_emb1(const float* __restrict__ pred,
                       const int* __restrict__ inst,
                       const float* __restrict__ tm){
    __shared__ float sS[8][80];
    int b = blockIdx.y;
    int t = threadIdx.x;
    int lane = t & 31, wid = t >> 5;
    float cnt[NL], a0[NL], a1[NL], a2[NL], a3[NL];
    #pragma unroll
    for (int l=0;l<NL;l++){ cnt[l]=0.f; a0[l]=0.f; a1[l]=0.f; a2[l]=0.f; a3[l]=0.f; }

    const float4* tm4 = (const float4*)(tm + b*HW);
    const int4*   in4 = (const int4*)(inst + b*HW);
    const float4* e0 = (const float4*)(pred + (b*NCH + 6)*HW);
    const float4* e1 = (const float4*)(pred + (b*NCH + 7)*HW);
    const float4* e2 = (const float4*)(pred + (b*NCH + 8)*HW);
    const float4* e3 = (const float4*)(pred + (b*NCH + 9)*HW);
    int stride = gridDim.x*blockDim.x;
    for (int i = blockIdx.x*blockDim.x + t; i < HW4; i += stride){
        float4 m = tm4[i]; int4 gi = in4[i];
        float4 va = e0[i], vb = e1[i], vc = e2[i], vd = e3[i];
        float mv[4] = {m.x, m.y, m.z, m.w};
        int   lv[4] = {gi.x & 15, gi.y & 15, gi.z & 15, gi.w & 15};
        float av[4] = {va.x, va.y, va.z, va.w};
        float bv[4] = {vb.x, vb.y, vb.z, vb.w};
        float cv[4] = {vc.x, vc.y, vc.z, vc.w};
        float dv[4] = {vd.x, vd.y, vd.z, vd.w};
        #pragma unroll
        for (int comp=0; comp<4; comp++){
            bool on = mv[comp] > 0.5f;
            int lab = lv[comp];
            #pragma unroll
            for (int l=0;l<NL;l++){
                bool hit = on && (lab == l);
                if (hit){
                    cnt[l] += 1.f;
                    a0[l] += av[comp];
                    a1[l] += bv[comp];
                    a2[l] += cv[comp];
                    a3[l] += dv[comp];
                }
            }
        }
    }
    #pragma unroll
    for (int l=0;l<NL;l++){
        float v0=cnt[l], v1=a0[l], v2=a1[l], v3=a2[l], v4=a3[l];
        #pragma unroll
        for (int o=16;o;o>>=1){
            v0 += __shfl_down_sync(0xffffffffu, v0, o);
            v1 += __shfl_down_sync(0xffffffffu, v1, o);
            v2 += __shfl_down_sync(0xffffffffu, v2, o);
            v3 += __shfl_down_sync(0xffffffffu, v3, o);
            v4 += __shfl_down_sync(0xffffffffu, v4, o);
        }
        if (lane == 0){
            sS[wid][l*5+0]=v0; sS[wid][l*5+1]=v1; sS[wid][l*5+2]=v2;
            sS[wid][l*5+3]=v3; sS[wid][l*5+4]=v4;
        }
    }
    __syncthreads();
    if (t < 80){
        float s = 0.f;
        #pragma unroll
        for (int w=0;w<8;w++) s += sS[w][t];
        if (s != 0.f){
            int l = t/5, comp = t - 5*l;
            if (comp == 0) atomicAdd(&gS.embCnt[b][l], s);
            else           atomicAdd(&gS.embSum[b][l][comp-1], s);
        }
    }
}

// ------- FUSED emb2 (hinge variance) + kernels dice; flat grid 3200x256 ----
__global__ void __launch_bounds__(256) k_emb2kern(const float* __restrict__ pred,
                           const int* __restrict__ inst,
                           const float* __restrict__ gtk,
                           const float* __restrict__ tm){
    __shared__ float sM[NL][4];
    __shared__ float sInv[NL];
    __shared__ float sRedL[8];
    __shared__ float sRedK[8][15];
    int b = blockIdx.x / 400;
    int i = (blockIdx.x - b*400)*256 + threadIdx.x;
    if (threadIdx.x < NL){
        int l = threadIdx.x;
        float c = gS.embCnt[b][l];
        float inv = 1.f / fmaxf(c, 1.f);
        sInv[l] = inv;
        #pragma unroll
        for (int d=0;d<4;d++) sM[l][d] = gS.embSum[b][l][d]*inv;
    }
    __syncthreads();
    float4 m = ((const float4*)(tm + b*HW))[i];
    int4 gi  = ((const int4*)(inst + b*HW))[i];
    float4 a = ((const float4*)(pred + (b*NCH + 6)*HW))[i];
    float4 bb= ((const float4*)(pred + (b*NCH + 7)*HW))[i];
    float4 c = ((const float4*)(pred + (b*NCH + 8)*HW))[i];
    float4 d = ((const float4*)(pred + (b*NCH + 9)*HW))[i];
    const float* pb = pred + (b*NCH + 1)*HW;
    const float* gb = gtk  + b*NKER*HW;

    float mv[4] = {m.x, m.y, m.z, m.w};
    int   lv[4] = {gi.x & 15, gi.y & 15, gi.z & 15, gi.w & 15};
    float av[4] = {a.x, a.y, a.z, a.w};
    float bv[4] = {bb.x, bb.y, bb.z, bb.w};
    float cv[4] = {c.x, c.y, c.z, c.w};
    float dv[4] = {d.x, d.y, d.z, d.w};

    float si[5], s1[5], s2[5];
    #pragma unroll
    for (int kc=0;kc<5;kc++){
        float4 p = ((const float4*)(pb + kc*HW))[i];
        float4 g = ((const float4*)(gb + kc*HW))[i];
        float ai=0.f,u=0.f,cc=0.f;
        if (mv[0] > 0.5f){ float pp = sigm(p.x); ai+=pp*g.x; u+=pp*pp; cc+=g.x; }
        if (mv[1] > 0.5f){ float pp = sigm(p.y); ai+=pp*g.y; u+=pp*pp; cc+=g.y; }
        if (mv[2] > 0.5f){ float pp = sigm(p.z); ai+=pp*g.z; u+=pp*pp; cc+=g.z; }
        if (mv[3] > 0.5f){ float pp = sigm(p.w); ai+=pp*g.w; u+=pp*pp; cc+=g.w; }
        si[kc]=ai; s1[kc]=u; s2[kc]=cc;
    }

    float acc = 0.f;
    #pragma unroll
    for (int comp=0; comp<4; comp++){
        if (mv[comp] > 0.5f){
            int l = lv[comp];
            float v0 = av[comp] - sM[l][0];
            float v1 = bv[comp] - sM[l][1];
            float v2 = cv[comp] - sM[l][2];
            float v3 = dv[comp] - sM[l][3];
            float dd = sqrtf(v0*v0+v1*v1+v2*v2+v3*v3 + 1e-12f);
            float h = dd - 0.5f;
            if (h > 0.f) acc += h*h*sInv[l];
        }
    }

    int lane = threadIdx.x & 31, wid = threadIdx.x >> 5;
    #pragma unroll
    for (int o=16;o;o>>=1) acc += __shfl_down_sync(0xffffffffu, acc, o);
    if (lane == 0) sRedL[wid] = acc;
    #pragma unroll
    for (int kc=0;kc<5;kc++){
        float ai = si[kc], u = s1[kc], cc = s2[kc];
        #pragma unroll
        for (int o=16;o;o>>=1){
            ai += __shfl_down_sync(0xffffffffu, ai, o);
            u  += __shfl_down_sync(0xffffffffu, u, o);
            cc += __shfl_down_sync(0xffffffffu, cc, o);
        }
        if (lane == 0){ sRedK[wid][kc*3]=ai; sRedK[wid][kc*3+1]=u; sRedK[wid][kc*3+2]=cc; }
    }
    __syncthreads();
    if (threadIdx.x == 0){
        float s = 0.f;
        #pragma unroll
        for (int w=0;w<8;w++) s += sRedL[w];
        if (s != 0.f) atomicAdd(&gS.lvSum[b], s);
    }
    if (threadIdx.x >= 32 && threadIdx.x < 47){
        int j = threadIdx.x - 32;
        float s = 0.f;
        #pragma unroll
        for (int w=0;w<8;w++) s += sRedK[w][j];
        int kc = j/3, comp = j - 3*kc;
        if (s != 0.f){
            if (comp==0) atomicAdd(&gS.kInter[b*NKER+kc], s);
            else if (comp==1) atomicAdd(&gS.kU1[b*NKER+kc], s);
            else atomicAdd(&gS.kU2[b*NKER+kc], s);
        }
    }
}

// ------- FUSED select + final assembly; 1 block x 1024 ---------------------
__global__ void __launch_bounds__(1024, 1) k_selfinal(float* out){
    __shared__ unsigned hC[4096];
    __shared__ float    hQ[4096];
    __shared__ unsigned scC[1024];
    __shared__ float    scQ[1024];
    __shared__ float    sNegselArr[Bn];
    __shared__ unsigned sPrefix;
    __shared__ int      sK;
    __shared__ float    sAcc;
    int t = threadIdx.x;

    for (int b=0;b<Bn;b++){
        int cnt = gS.negcount[b];
        int k0 = 3*gS.npos[b]; if (k0 > cnt) k0 = cnt;
        if (k0 >= cnt){                          // common path: all negatives
            if (t == 0) sNegselArr[b] = gS.totNegQ[b];
        } else if (k0 <= 0){
            if (t == 0) sNegselArr[b] = 0.f;
        } else {
            if (t == 0){ sK = k0; sAcc = 0.f; sPrefix = 0u; }
            __syncthreads();
            const unsigned* nb = g_negbits + b*HW;
            for (int level = 1; level <= 3; level++){
                int K = sK;
                unsigned pfx = sPrefix;
                for (int i=t;i<4096;i+=1024){ hC[i]=0u; hQ[i]=0.f; }
                __syncthreads();
                for (int j = t; j - t < cnt; j += 1024){
                    bool in = j < cnt;
                    unsigned bits = in ? nb[j] : 0u;
                    unsigned bin = 0; bool ok = false;
                    if (in){
                        if (level == 1){ bin = bits >> 20; ok = true; }
                        else if (level == 2){ ok = (bits>>20)==(pfx>>20); bin = (bits>>8)&0xFFFu; }
                        else { ok = (bits>>8)==(pfx>>8); bin = bits & 0xFFu; }
                    }
                    float v = __uint_as_float(bits);
                    float q = v*v;
                    unsigned key = ok ? bin : 0xFFFFFFFFu;
                    unsigned grp = __match_any_sync(0xffffffffu, key);
                    if (grp == 0xffffffffu){
                        if (ok){
                            #pragma unroll
                            for (int o=16;o;o>>=1) q += __shfl_down_sync(0xffffffffu, q, o);
                            if ((t & 31) == 0){ atomicAdd(&hC[bin], 32u); atomicAdd(&hQ[bin], q); }
                        }
                    } else if (ok){
                        atomicAdd(&hC[bin], 1u); atomicAdd(&hQ[bin], q);
                    }
                }
                __syncthreads();
                int nbins = (level == 3) ? 256 : 4096;
                int per = (nbins >= 1024) ? (nbins >> 10) : 1;
                int hi = nbins - 1 - t*per;
                unsigned c = 0; float q = 0.f;
                if (hi >= 0){
                    for (int i=0;i<per;i++){ int bx = hi - i; if (bx >= 0){ c += hC[bx]; q += hQ[bx]; } }
                }
                scC[t] = c; scQ[t] = q;
                __syncthreads();
                for (int off=1; off<1024; off<<=1){
                    unsigned cv = (t >= off) ? scC[t-off] : 0u;
                    float    qv = (t >= off) ? scQ[t-off] : 0.f;
                    __syncthreads();
                    scC[t] += cv; scQ[t] += qv;
                    __syncthreads();
                }
                unsigned incl = scC[t], excl = incl - c;
                if (hi >= 0 && (int)excl < K && K <= (int)incl){
                    unsigned acc = excl;
                    float qacc = scQ[t] - q;
                    int chosen = hi;
                    for (int i=0;i<per;i++){
                        int bx = hi - i;
                        unsigned cc = hC[bx];
                        if (acc + cc >= (unsigned)K){ chosen = bx; break; }
                        acc += cc; qacc += hQ[bx];
                    }
                    sK = K - (int)acc;
                    sAcc += qacc;
                    if (level == 1)      sPrefix = ((unsigned)chosen) << 20;
                    else if (level == 2) sPrefix |= ((unsigned)chosen) << 8;
                    else                 sPrefix |= (unsigned)chosen;
                }
                __syncthreads();
            }
            if (t == 0){
                float tv = __uint_as_float(sPrefix);
                sNegselArr[b] = sAcc + (float)sK * tv * tv;
            }
        }
        __syncthreads();
    }

    if (t != 0) return;
    // final math (single thread; spills to local are fine here)
    float loss_text = 0.f;
    for (int b=0;b<Bn;b++){
        float inter = gS.posSum[b];
        float uni = gS.posSum2[b] + sNegselArr[b] + (float)gS.npos[b] + 1e-6f;
        loss_text += 1.f - 2.f*inter/uni;
    }
    loss_text /= (float)Bn;
    float loss_k = 0.f;
    for (int r=0;r<Bn*NKER;r++){
        float uni = gS.kU1[r] + gS.kU2[r] + 1e-6f;
        loss_k += 1.f - 2.f*gS.kInter[r]/uni;
    }
    loss_k /= (float)(Bn*NKER);
    float lvT=0.f, ldT=0.f, lrT=0.f;
    for (int b=0;b<Bn;b++){
        int n=0;
        bool pres[NL];
        float mean[NL][4];
        for (int l=0;l<NL;l++){
            float cc = gS.embCnt[b][l];
            pres[l] = cc > 0.f;
            if (pres[l]) n++;
            float inv = 1.f/fmaxf(cc,1.f);
            for (int d=0;d<4;d++) mean[l][d] = gS.embSum[b][l][d]*inv;
        }
        float nf = (float)n;
        float lv = gS.lvSum[b] / fmaxf(nf, 1.f);
        float ld = 0.f;
        for (int ii=0;ii<NL;ii++) for (int j=ii+1;j<NL;j++){
            if (pres[ii] && pres[j]){
                float d2=0.f;
                for (int d=0;d<4;d++){
                    float df = mean[ii][d]-mean[j][d];
                    d2 += df*df;
                }
                float pd = sqrtf(d2 + 1e-12f);
                float h = fmaxf(3.0f - pd, 0.f);
                ld += h*h;
            }
        }
        ld /= fmaxf(nf*(nf-1.f), 1.f);
        float lr = 0.f;
        for (int l=0;l<NL;l++){
            if (pres[l]){
                float d2=0.f;
                for (int d=0;d<4;d++) d2 += mean[l][d]*mean[l][d];
                lr += sqrtf(d2 + 1e-12f);
            }
        }
        lr /= fmaxf(nf, 1.f);
        float act = (n > 1) ? 1.f : 0.f;
        lvT += act*lv; ldT += act*ld; lrT += act*lr;
    }
    float loss_emb = 0.25f*(lvT + ldT + 0.001f*(lrT/(float)Bn));
    float loss = loss_k + 0.5f*loss_text + loss_emb;
    out[0]=loss; out[1]=loss_text; out[2]=loss_k; out[3]=loss_emb;
}

// ---- launch: 5 workloads, emb1-first overlap ------------------------------
extern "C" void kernel_launch(void* const* d_in, const int* in_sizes, int n_in,
                              void* d_out, int out_size){
    const float* pred   = (const float*)d_in[0];
    const float* gtText = (const float*)d_in[1];
    const float* gtk    = (const float*)d_in[2];
    const float* tm     = (const float*)d_in[3];
    const int*   inst   = (const int*)d_in[4];
    float* out = (float*)d_out;

    static cudaStream_t s1 = nullptr, s2 = nullptr;
    static cudaEvent_t ev0 = nullptr, ev1 = nullptr, ev2 = nullptr;
    static void* pS = nullptr;
    if (s1 == nullptr){
        cudaStreamCreateWithFlags(&s1, cudaStreamNonBlocking);
        cudaStreamCreateWithFlags(&s2, cudaStreamNonBlocking);
        cudaEventCreateWithFlags(&ev0, cudaEventDisableTiming);
        cudaEventCreateWithFlags(&ev1, cudaEventDisableTiming);
        cudaEventCreateWithFlags(&ev2, cudaEventDisableTiming);
        cudaGetSymbolAddress(&pS, gS);
    }

    cudaMemsetAsync(pS, 0, sizeof(Scal), 0);             // 1
    cudaEventRecord(ev0, 0);

    // chain A (s2): emb1 -> emb2kern
    cudaStreamWaitEvent(s2, ev0, 0);
    k_emb1<<<dim3(32, Bn), 256, 0, s2>>>(pred, inst, tm);          // 2
    k_emb2kern<<<3200, 256, 0, s2>>>(pred, inst, gtk, tm);         // 3
    cudaEventRecord(ev2, s2);

    // chain B (s1): dilstats
    cudaStreamWaitEvent(s1, ev0, 0);
    k_dilstats<<<dim3(20,20,Bn), dim3(32,8), 0, s1>>>(pred, gtText, tm);  // 4
    cudaEventRecord(ev1, s1);

    // join -> fused select+final
    cudaStreamWaitEvent(0, ev1, 0);
    cudaStreamWaitEvent(0, ev2, 0);
    k_selfinal<<<1, 1024>>>(out);                                  // 5
}

// round 14
// speedup vs baseline: 2.7560x; 1.9306x over previous
#include <cuda_runtime.h>
#include <math.h>

#define Bn 8
#define Hh 640
#define Ww 640
#define HW (Hh*Ww)          // 409600
#define HW4 (HW/4)          // 102400
#define NCH 10
#define NKER 5
#define NL 16
#define NEGINF (-1e30f)

// ---------------- scratch ----------------
struct Scal {
    int   negcount[Bn];
    int   npos[Bn];
    float posSum[Bn], posSum2[Bn], totNegQ[Bn], lvSum[Bn];
    float kInter[Bn*NKER], kU1[Bn*NKER], kU2[Bn*NKER];
    float embCnt[Bn][NL];
    float embSum[Bn][NL][4];
};
__device__ Scal gS;
__device__ unsigned g_negbits[Bn*HW];

__device__ __forceinline__ float sigm(float x){ return 1.0f/(1.0f+expf(-x)); }

// ------- fused dilate (sigmoid-of-max) + OHEM stats + staged compaction ----
// grid (20,20,Bn), block (32,8). Tile 32x32, halo 4.
__global__ void k_dilstats(const float* __restrict__ pred,
                           const float* __restrict__ gt,
                           const float* __restrict__ tm){
    __shared__ float sIn[40][41];
    __shared__ float sHm[40][33];
    __shared__ unsigned sNeg[1024];
    __shared__ int sCnt, sBase;
    __shared__ float sR0[8], sR1[8], sR2[8], sR3[8];
    int b = blockIdx.z;
    int gx0 = blockIdx.x*32 - 4, gy0 = blockIdx.y*32 - 4;
    int tid = threadIdx.y*32 + threadIdx.x;
    int lane = tid & 31, wid = tid >> 5;
    const float* p0 = pred + b*NCH*HW;

    if (tid == 0) sCnt = 0;
    for (int idx = tid; idx < 1600; idx += 256){
        int r = idx/40, c = idx - 40*r;
        int gy = gy0 + r, gx = gx0 + c;
        sIn[r][c] = (gy>=0 && gy<Hh && gx>=0 && gx<Ww) ? p0[gy*Ww + gx] : NEGINF;
    }
    __syncthreads();
    for (int idx = tid; idx < 1280; idx += 256){
        int r = idx >> 5, c = idx & 31;
        float m = sIn[r][c];
        #pragma unroll
        for (int j=1;j<9;j++) m = fmaxf(m, sIn[r][c+j]);
        sHm[r][c] = m;
    }
    __syncthreads();

    int pc = 0; float ps = 0.f, ps2 = 0.f, qn = 0.f;
    #pragma unroll
    for (int k=0;k<4;k++){
        int r = threadIdx.y*4 + k;
        int c = threadIdx.x;
        float m = sHm[r][c];
        #pragma unroll
        for (int j=1;j<9;j++) m = fmaxf(m, sHm[r+j][c]);
        float v = sigm(m);                  // sigmoid after max (monotone)
        int gy = gy0 + 4 + r, gx = gx0 + 4 + c;
        int gi = b*HW + gy*Ww + gx;
        float g  = gt[gi];
        float mm = tm[gi];
        bool isPos = (g > 0.5f) && (mm > 0.5f);
        bool isNeg = (g <= 0.5f) && (mm > 0.5f);
        if (isPos){ pc++; ps += v; ps2 += v*v; }
        if (isNeg) qn += v*v;
        unsigned ball = __ballot_sync(0xffffffffu, isNeg);
        if (isNeg){
            int rank = __popc(ball & ((1u<<lane)-1u));
            int leader = __ffs(ball)-1;
            int base = 0;
            if (lane == leader) base = atomicAdd(&sCnt, __popc(ball));
            base = __shfl_sync(ball, base, leader);
            sNeg[base + rank] = __float_as_uint(v);
        }
    }
    #pragma unroll
    for (int o=16;o;o>>=1){
        pc  += __shfl_down_sync(0xffffffffu, pc, o);
        ps  += __shfl_down_sync(0xffffffffu, ps, o);
        ps2 += __shfl_down_sync(0xffffffffu, ps2, o);
        qn  += __shfl_down_sync(0xffffffffu, qn, o);
    }
    if (lane == 0){ sR0[wid]=(float)pc; sR1[wid]=ps; sR2[wid]=ps2; sR3[wid]=qn; }
    __syncthreads();        // covers sNeg, sCnt, sR*
    if (tid == 0){
        float a=0,bb=0,cc=0,dd=0;
        #pragma unroll
        for (int w=0;w<8;w++){ a+=sR0[w]; bb+=sR1[w]; cc+=sR2[w]; dd+=sR3[w]; }
        if (a  != 0.f) atomicAdd(&gS.npos[b], (int)a);
        if (bb != 0.f) atomicAdd(&gS.posSum[b], bb);
        if (cc != 0.f) atomicAdd(&gS.posSum2[b], cc);
        if (dd != 0.f) atomicAdd(&gS.totNegQ[b], dd);
        sBase = atomicAdd(&gS.negcount[b], sCnt);
    }
    __syncthreads();
    int cnt = sCnt, base = sBase;
    unsigned* dst = g_negbits + b*HW + base;
    for (int i = tid; i < cnt; i += 256) dst[i] = sNeg[i];
}

// ------- emb pass 1: REGISTER accumulators + predicated adds ---------------
// grid (32, Bn) x 256
__global__ void __launch_bounds__(256) k_emb1(const float* __restrict__ pred,
                       const int* __restrict__ inst,
                       const float* __restrict__ tm){
    __shared__ float sS[8][80];
    int b = blockIdx.y;
    int t = threadIdx.x;
    int lane = t & 31, wid = t >> 5;
    float cnt[NL], a0[NL], a1[NL], a2[NL], a3[NL];
    #pragma unroll
    for (int l=0;l<NL;l++){ cnt[l]=0.f; a0[l]=0.f; a1[l]=0.f; a2[l]=0.f; a3[l]=0.f; }

    const float4* tm4 = (const float4*)(tm + b*HW);
    const int4*   in4 = (const int4*)(inst + b*HW);
    const float4* e0 = (const float4*)(pred + (b*NCH + 6)*HW);
    const float4* e1 = (const float4*)(pred + (b*NCH + 7)*HW);
    const float4* e2 = (const float4*)(pred + (b*NCH + 8)*HW);
    const float4* e3 = (const float4*)(pred + (b*NCH + 9)*HW);
    int stride = gridDim.x*blockDim.x;
    for (int i = blockIdx.x*blockDim.x + t; i < HW4; i += stride){
        float4 m = tm4[i]; int4 gi = in4[i];
        float4 va = e0[i], vb = e1[i], vc = e2[i], vd = e3[i];
        float mv[4] = {m.x, m.y, m.z, m.w};
        int   lv[4] = {gi.x & 15, gi.y & 15, gi.z & 15, gi.w & 15};
        float av[4] = {va.x, va.y, va.z, va.w};
        float bv[4] = {vb.x, vb.y, vb.z, vb.w};
        float cv[4] = {vc.x, vc.y, vc.z, vc.w};
        float dv[4] = {vd.x, vd.y, vd.z, vd.w};
        #pragma unroll
        for (int comp=0; comp<4; comp++){
            bool on = mv[comp] > 0.5f;
            int lab = lv[comp];
            #pragma unroll
            for (int l=0;l<NL;l++){
                bool hit = on && (lab == l);
                if (hit){
                    cnt[l] += 1.f;
                    a0[l] += av[comp];
                    a1[l] += bv[comp];
                    a2[l] += cv[comp];
                    a3[l] += dv[comp];
                }
            }
        }
    }
    #pragma unroll
    for (int l=0;l<NL;l++){
        float v0=cnt[l], v1=a0[l], v2=a1[l], v3=a2[l], v4=a3[l];
        #pragma unroll
        for (int o=16;o;o>>=1){
            v0 += __shfl_down_sync(0xffffffffu, v0, o);
            v1 += __shfl_down_sync(0xffffffffu, v1, o);
            v2 += __shfl_down_sync(0xffffffffu, v2, o);
            v3 += __shfl_down_sync(0xffffffffu, v3, o);
            v4 += __shfl_down_sync(0xffffffffu, v4, o);
        }
        if (lane == 0){
            sS[wid][l*5+0]=v0; sS[wid][l*5+1]=v1; sS[wid][l*5+2]=v2;
            sS[wid][l*5+3]=v3; sS[wid][l*5+4]=v4;
        }
    }
    __syncthreads();
    if (t < 80){
        float s = 0.f;
        #pragma unroll
        for (int w=0;w<8;w++) s += sS[w][t];
        if (s != 0.f){
            int l = t/5, comp = t - 5*l;
            if (comp == 0) atomicAdd(&gS.embCnt[b][l], s);
            else           atomicAdd(&gS.embSum[b][l][comp-1], s);
        }
    }
}

// ------- FUSED emb2 (hinge variance) + kernels dice; flat grid 3200x256 ----
__global__ void __launch_bounds__(256) k_emb2kern(const float* __restrict__ pred,
                           const int* __restrict__ inst,
                           const float* __restrict__ gtk,
                           const float* __restrict__ tm){
    __shared__ float sM[NL][4];
    __shared__ float sInv[NL];
    __shared__ float sRedL[8];
    __shared__ float sRedK[8][15];
    int b = blockIdx.x / 400;
    int i = (blockIdx.x - b*400)*256 + threadIdx.x;
    if (threadIdx.x < NL){
        int l = threadIdx.x;
        float c = gS.embCnt[b][l];
        float inv = 1.f / fmaxf(c, 1.f);
        sInv[l] = inv;
        #pragma unroll
        for (int d=0;d<4;d++) sM[l][d] = gS.embSum[b][l][d]*inv;
    }
    __syncthreads();
    float4 m = ((const float4*)(tm + b*HW))[i];
    int4 gi  = ((const int4*)(inst + b*HW))[i];
    float4 a = ((const float4*)(pred + (b*NCH + 6)*HW))[i];
    float4 bb= ((const float4*)(pred + (b*NCH + 7)*HW))[i];
    float4 c = ((const float4*)(pred + (b*NCH + 8)*HW))[i];
    float4 d = ((const float4*)(pred + (b*NCH + 9)*HW))[i];
    const float* pb = pred + (b*NCH + 1)*HW;
    const float* gb = gtk  + b*NKER*HW;

    float mv[4] = {m.x, m.y, m.z, m.w};
    int   lv[4] = {gi.x & 15, gi.y & 15, gi.z & 15, gi.w & 15};
    float av[4] = {a.x, a.y, a.z, a.w};
    float bv[4] = {bb.x, bb.y, bb.z, bb.w};
    float cv[4] = {c.x, c.y, c.z, c.w};
    float dv[4] = {d.x, d.y, d.z, d.w};

    float si[5], s1[5], s2[5];
    #pragma unroll
    for (int kc=0;kc<5;kc++){
        float4 p = ((const float4*)(pb + kc*HW))[i];
        float4 g = ((const float4*)(gb + kc*HW))[i];
        float ai=0.f,u=0.f,cc=0.f;
        if (mv[0] > 0.5f){ float pp = sigm(p.x); ai+=pp*g.x; u+=pp*pp; cc+=g.x; }
        if (mv[1] > 0.5f){ float pp = sigm(p.y); ai+=pp*g.y; u+=pp*pp; cc+=g.y; }
        if (mv[2] > 0.5f){ float pp = sigm(p.z); ai+=pp*g.z; u+=pp*pp; cc+=g.z; }
        if (mv[3] > 0.5f){ float pp = sigm(p.w); ai+=pp*g.w; u+=pp*pp; cc+=g.w; }
        si[kc]=ai; s1[kc]=u; s2[kc]=cc;
    }

    float acc = 0.f;
    #pragma unroll
    for (int comp=0; comp<4; comp++){
        if (mv[comp] > 0.5f){
            int l = lv[comp];
            float v0 = av[comp] - sM[l][0];
            float v1 = bv[comp] - sM[l][1];
            float v2 = cv[comp] - sM[l][2];
            float v3 = dv[comp] - sM[l][3];
            float dd = sqrtf(v0*v0+v1*v1+v2*v2+v3*v3 + 1e-12f);
            float h = dd - 0.5f;
            if (h > 0.f) acc += h*h*sInv[l];
        }
    }

    int lane = threadIdx.x & 31, wid = threadIdx.x >> 5;
    #pragma unroll
    for (int o=16;o;o>>=1) acc += __shfl_down_sync(0xffffffffu, acc, o);
    if (lane == 0) sRedL[wid] = acc;
    #pragma unroll
    for (int kc=0;kc<5;kc++){
        float ai = si[kc], u = s1[kc], cc = s2[kc];
        #pragma unroll
        for (int o=16;o;o>>=1){
            ai += __shfl_down_sync(0xffffffffu, ai, o);
            u  += __shfl_down_sync(0xffffffffu, u, o);
            cc += __shfl_down_sync(0xffffffffu, cc, o);
        }
        if (lane == 0){ sRedK[wid][kc*3]=ai; sRedK[wid][kc*3+1]=u; sRedK[wid][kc*3+2]=cc; }
    }
    __syncthreads();
    if (threadIdx.x == 0){
        float s = 0.f;
        #pragma unroll
        for (int w=0;w<8;w++) s += sRedL[w];
        if (s != 0.f) atomicAdd(&gS.lvSum[b], s);
    }
    if (threadIdx.x >= 32 && threadIdx.x < 47){
        int j = threadIdx.x - 32;
        float s = 0.f;
        #pragma unroll
        for (int w=0;w<8;w++) s += sRedK[w][j];
        int kc = j/3, comp = j - 3*kc;
        if (s != 0.f){
            if (comp==0) atomicAdd(&gS.kInter[b*NKER+kc], s);
            else if (comp==1) atomicAdd(&gS.kU1[b*NKER+kc], s);
            else atomicAdd(&gS.kU2[b*NKER+kc], s);
        }
    }
}

// ------- FUSED select + PARALLEL final assembly; 1 block x 1024 ------------
__global__ void __launch_bounds__(1024, 1) k_selfinal(float* out){
    __shared__ unsigned hC[4096];
    __shared__ float    hQ[4096];
    __shared__ unsigned scC[1024];
    __shared__ float    scQ[1024];
    __shared__ float    sNegselArr[Bn];
    __shared__ unsigned sPrefix;
    __shared__ int      sK;
    __shared__ float    sAcc;
    // parallel-final staging
    __shared__ float sMean[Bn][NL][4];
    __shared__ float sPres[Bn][NL];
    __shared__ float sN[Bn];
    __shared__ float sLd[Bn];
    __shared__ float sLr[Bn];
    int t = threadIdx.x;

    // ---- OHEM negative-selection sum (common path: scalar read) ----
    for (int b=0;b<Bn;b++){
        int cnt = gS.negcount[b];
        int k0 = 3*gS.npos[b]; if (k0 > cnt) k0 = cnt;
        if (k0 >= cnt){
            if (t == 0) sNegselArr[b] = gS.totNegQ[b];
        } else if (k0 <= 0){
            if (t == 0) sNegselArr[b] = 0.f;
        } else {
            if (t == 0){ sK = k0; sAcc = 0.f; sPrefix = 0u; }
            __syncthreads();
            const unsigned* nb = g_negbits + b*HW;
            for (int level = 1; level <= 3; level++){
                int K = sK;
                unsigned pfx = sPrefix;
                for (int i=t;i<4096;i+=1024){ hC[i]=0u; hQ[i]=0.f; }
                __syncthreads();
                for (int j = t; j - t < cnt; j += 1024){
                    bool in = j < cnt;
                    unsigned bits = in ? nb[j] : 0u;
                    unsigned bin = 0; bool ok = false;
                    if (in){
                        if (level == 1){ bin = bits >> 20; ok = true; }
                        else if (level == 2){ ok = (bits>>20)==(pfx>>20); bin = (bits>>8)&0xFFFu; }
                        else { ok = (bits>>8)==(pfx>>8); bin = bits & 0xFFu; }
                    }
                    float v = __uint_as_float(bits);
                    float q = v*v;
                    unsigned key = ok ? bin : 0xFFFFFFFFu;
                    unsigned grp = __match_any_sync(0xffffffffu, key);
                    if (grp == 0xffffffffu){
                        if (ok){
                            #pragma unroll
                            for (int o=16;o;o>>=1) q += __shfl_down_sync(0xffffffffu, q, o);
                            if ((t & 31) == 0){ atomicAdd(&hC[bin], 32u); atomicAdd(&hQ[bin], q); }
                        }
                    } else if (ok){
                        atomicAdd(&hC[bin], 1u); atomicAdd(&hQ[bin], q);
                    }
                }
                __syncthreads();
                int nbins = (level == 3) ? 256 : 4096;
                int per = (nbins >= 1024) ? (nbins >> 10) : 1;
                int hi = nbins - 1 - t*per;
                unsigned c = 0; float q = 0.f;
                if (hi >= 0){
                    for (int i=0;i<per;i++){ int bx = hi - i; if (bx >= 0){ c += hC[bx]; q += hQ[bx]; } }
                }
                scC[t] = c; scQ[t] = q;
                __syncthreads();
                for (int off=1; off<1024; off<<=1){
                    unsigned cv = (t >= off) ? scC[t-off] : 0u;
                    float    qv = (t >= off) ? scQ[t-off] : 0.f;
                    __syncthreads();
                    scC[t] += cv; scQ[t] += qv;
                    __syncthreads();
                }
                unsigned incl = scC[t], excl = incl - c;
                if (hi >= 0 && (int)excl < K && K <= (int)incl){
                    unsigned acc = excl;
                    float qacc = scQ[t] - q;
                    int chosen = hi;
                    for (int i=0;i<per;i++){
                        int bx = hi - i;
                        unsigned cc = hC[bx];
                        if (acc + cc >= (unsigned)K){ chosen = bx; break; }
                        acc += cc; qacc += hQ[bx];
                    }
                    sK = K - (int)acc;
                    sAcc += qacc;
                    if (level == 1)      sPrefix = ((unsigned)chosen) << 20;
                    else if (level == 2) sPrefix |= ((unsigned)chosen) << 8;
                    else                 sPrefix |= (unsigned)chosen;
                }
                __syncthreads();
            }
            if (t == 0){
                float tv = __uint_as_float(sPrefix);
                sNegselArr[b] = sAcc + (float)sK * tv * tv;
            }
        }
        __syncthreads();
    }

    // ---- parallel final assembly ----
    if (t < Bn){ sN[t]=0.f; sLd[t]=0.f; sLr[t]=0.f; }
    __syncthreads();
    if (t < Bn*NL){                     // 128 threads: means + presence
        int b = t >> 4, l = t & 15;
        float cc = gS.embCnt[b][l];
        float pres = (cc > 0.f) ? 1.f : 0.f;
        sPres[b][l] = pres;
        float inv = 1.f/fmaxf(cc,1.f);
        #pragma unroll
        for (int d=0;d<4;d++) sMean[b][l][d] = gS.embSum[b][l][d]*inv;
        if (pres != 0.f) atomicAdd(&sN[b], 1.f);
    }
    __syncthreads();
    if (t < Bn*NL){                     // 128 threads: lr terms
        int b = t >> 4, l = t & 15;
        if (sPres[b][l] != 0.f){
            float d2=0.f;
            #pragma unroll
            for (int d=0;d<4;d++) d2 += sMean[b][l][d]*sMean[b][l][d];
            atomicAdd(&sLr[b], sqrtf(d2 + 1e-12f));
        }
    }
    if (t < Bn*120){                    // 960 threads: ld pair terms
        int b = t / 120, p = t - b*120;
        // map p -> (ii,jj), ii<jj
        int ii = 0, rem = p;
        #pragma unroll
        for (int k=0;k<15;k++){
            int row = 15 - k;           // pairs with ii=k
            if (rem < row){ ii = k; break; }
            rem -= row;
        }
        int jj = ii + 1 + rem;
        if (sPres[b][ii] != 0.f && sPres[b][jj] != 0.f){
            float d2=0.f;
            #pragma unroll
            for (int d=0;d<4;d++){
                float df = sMean[b][ii][d]-sMean[b][jj][d];
                d2 += df*df;
            }
            float pd = sqrtf(d2 + 1e-12f);
            float h = fmaxf(3.0f - pd, 0.f);
            if (h > 0.f) atomicAdd(&sLd[b], h*h);
        }
    }
    __syncthreads();
    if (t != 0) return;
    // scalar assembly: ~100 ops on scalars, no arrays
    float loss_text = 0.f;
    for (int b=0;b<Bn;b++){
        float inter = gS.posSum[b];
        float uni = gS.posSum2[b] + sNegselArr[b] + (float)gS.npos[b] + 1e-6f;
        loss_text += 1.f - 2.f*inter/uni;
    }
    loss_text /= (float)Bn;
    float loss_k = 0.f;
    for (int r=0;r<Bn*NKER;r++){
        float uni = gS.kU1[r] + gS.kU2[r] + 1e-6f;
        loss_k += 1.f - 2.f*gS.kInter[r]/uni;
    }
    loss_k /= (float)(Bn*NKER);
    float lvT=0.f, ldT=0.f, lrT=0.f;
    for (int b=0;b<Bn;b++){
        float nf = sN[b];
        float act = (nf > 1.f) ? 1.f : 0.f;
        lvT += act * (gS.lvSum[b] / fmaxf(nf, 1.f));
        ldT += act * (sLd[b] / fmaxf(nf*(nf-1.f), 1.f));
        lrT += act * (sLr[b] / fmaxf(nf, 1.f));
    }
    float loss_emb = 0.25f*(lvT + ldT + 0.001f*(lrT/(float)Bn));
    float loss = loss_k + 0.5f*loss_text + loss_emb;
    out[0]=loss; out[1]=loss_text; out[2]=loss_k; out[3]=loss_emb;
}

// ---- launch: 5 workloads, emb1-first overlap ------------------------------
extern "C" void kernel_launch(void* const* d_in, const int* in_sizes, int n_in,
                              void* d_out, int out_size){
    const float* pred   = (const float*)d_in[0];
    const float* gtText = (const float*)d_in[1];
    const float* gtk    = (const float*)d_in[2];
    const float* tm     = (const float*)d_in[3];
    const int*   inst   = (const int*)d_in[4];
    float* out = (float*)d_out;

    static cudaStream_t s1 = nullptr, s2 = nullptr;
    static cudaEvent_t ev0 = nullptr, ev1 = nullptr, ev2 = nullptr;
    static void* pS = nullptr;
    if (s1 == nullptr){
        cudaStreamCreateWithFlags(&s1, cudaStreamNonBlocking);
        cudaStreamCreateWithFlags(&s2, cudaStreamNonBlocking);
        cudaEventCreateWithFlags(&ev0, cudaEventDisableTiming);
        cudaEventCreateWithFlags(&ev1, cudaEventDisableTiming);
        cudaEventCreateWithFlags(&ev2, cudaEventDisableTiming);
        cudaGetSymbolAddress(&pS, gS);
    }

    cudaMemsetAsync(pS, 0, sizeof(Scal), 0);             // 1
    cudaEventRecord(ev0, 0);

    // chain A (s2): emb1 -> emb2kern
    cudaStreamWaitEvent(s2, ev0, 0);
    k_emb1<<<dim3(32, Bn), 256, 0, s2>>>(pred, inst, tm);          // 2
    k_emb2kern<<<3200, 256, 0, s2>>>(pred, inst, gtk, tm);         // 3
    cudaEventRecord(ev2, s2);

    // chain B (s1): dilstats
    cudaStreamWaitEvent(s1, ev0, 0);
    k_dilstats<<<dim3(20,20,Bn), dim3(32,8), 0, s1>>>(pred, gtText, tm);  // 4
    cudaEventRecord(ev1, s1);

    // join -> fused select+final
    cudaStreamWaitEvent(0, ev1, 0);
    cudaStreamWaitEvent(0, ev2, 0);
    k_selfinal<<<1, 1024>>>(out);                                  // 5
}

// round 15
// speedup vs baseline: 2.8567x; 1.0365x over previous
#include <cuda_runtime.h>
#include <math.h>

#define Bn 8
#define Hh 640
#define Ww 640
#define HW (Hh*Ww)          // 409600
#define HW4 (HW/4)          // 102400
#define NCH 10
#define NKER 5
#define NL 16
#define NEGINF (-1e30f)

// ---------------- scratch ----------------
struct Scal {
    int   negcount[Bn];
    int   npos[Bn];
    float posSum[Bn], posSum2[Bn], totNegQ[Bn], lvSum[Bn];
    float kInter[Bn*NKER], kU1[Bn*NKER], kU2[Bn*NKER];
    float embCnt[Bn][NL];
    float embSum[Bn][NL][4];
};
#define SCAL_WORDS (sizeof(Scal)/4)
__device__ Scal gS;
__device__ unsigned g_negbits[Bn*HW];

__device__ __forceinline__ float sigm(float x){ return 1.0f/(1.0f+expf(-x)); }

// ------- fused dilate (sigmoid-of-max) + OHEM stats + staged compaction ----
// grid (20,20,Bn), block (32,8). Tile 32x32, halo 4.
__global__ void k_dilstats(const float* __restrict__ pred,
                           const float* __restrict__ gt,
                           const float* __restrict__ tm){
    __shared__ float sIn[40][41];
    __shared__ float sHm[40][33];
    __shared__ unsigned sNeg[1024];
    __shared__ int sCnt, sBase;
    __shared__ float sR0[8], sR1[8], sR2[8], sR3[8];
    int b = blockIdx.z;
    int gx0 = blockIdx.x*32 - 4, gy0 = blockIdx.y*32 - 4;
    int tid = threadIdx.y*32 + threadIdx.x;
    int lane = tid & 31, wid = tid >> 5;
    const float* p0 = pred + b*NCH*HW;

    if (tid == 0) sCnt = 0;
    for (int idx = tid; idx < 1600; idx += 256){
        int r = idx/40, c = idx - 40*r;
        int gy = gy0 + r, gx = gx0 + c;
        sIn[r][c] = (gy>=0 && gy<Hh && gx>=0 && gx<Ww) ? p0[gy*Ww + gx] : NEGINF;
    }
    __syncthreads();
    for (int idx = tid; idx < 1280; idx += 256){
        int r = idx >> 5, c = idx & 31;
        float m = sIn[r][c];
        #pragma unroll
        for (int j=1;j<9;j++) m = fmaxf(m, sIn[r][c+j]);
        sHm[r][c] = m;
    }
    __syncthreads();

    int pc = 0; float ps = 0.f, ps2 = 0.f, qn = 0.f;
    #pragma unroll
    for (int k=0;k<4;k++){
        int r = threadIdx.y*4 + k;
        int c = threadIdx.x;
        float m = sHm[r][c];
        #pragma unroll
        for (int j=1;j<9;j++) m = fmaxf(m, sHm[r+j][c]);
        float v = sigm(m);                  // sigmoid after max (monotone)
        int gy = gy0 + 4 + r, gx = gx0 + 4 + c;
        int gi = b*HW + gy*Ww + gx;
        float g  = gt[gi];
        float mm = tm[gi];
        bool isPos = (g > 0.5f) && (mm > 0.5f);
        bool isNeg = (g <= 0.5f) && (mm > 0.5f);
        if (isPos){ pc++; ps += v; ps2 += v*v; }
        if (isNeg) qn += v*v;
        unsigned ball = __ballot_sync(0xffffffffu, isNeg);
        if (isNeg){
            int rank = __popc(ball & ((1u<<lane)-1u));
            int leader = __ffs(ball)-1;
            int base = 0;
            if (lane == leader) base = atomicAdd(&sCnt, __popc(ball));
            base = __shfl_sync(ball, base, leader);
            sNeg[base + rank] = __float_as_uint(v);
        }
    }
    #pragma unroll
    for (int o=16;o;o>>=1){
        pc  += __shfl_down_sync(0xffffffffu, pc, o);
        ps  += __shfl_down_sync(0xffffffffu, ps, o);
        ps2 += __shfl_down_sync(0xffffffffu, ps2, o);
        qn  += __shfl_down_sync(0xffffffffu, qn, o);
    }
    if (lane == 0){ sR0[wid]=(float)pc; sR1[wid]=ps; sR2[wid]=ps2; sR3[wid]=qn; }
    __syncthreads();        // covers sNeg, sCnt, sR*
    if (tid == 0){
        float a=0,bb=0,cc=0,dd=0;
        #pragma unroll
        for (int w=0;w<8;w++){ a+=sR0[w]; bb+=sR1[w]; cc+=sR2[w]; dd+=sR3[w]; }
        if (a  != 0.f) atomicAdd(&gS.npos[b], (int)a);
        if (bb != 0.f) atomicAdd(&gS.posSum[b], bb);
        if (cc != 0.f) atomicAdd(&gS.posSum2[b], cc);
        if (dd != 0.f) atomicAdd(&gS.totNegQ[b], dd);
        sBase = atomicAdd(&gS.negcount[b], sCnt);
    }
    __syncthreads();
    int cnt = sCnt, base = sBase;
    unsigned* dst = g_negbits + b*HW + base;
    for (int i = tid; i < cnt; i += 256) dst[i] = sNeg[i];
}

// ------- emb pass 1: REGISTER accumulators + predicated adds ---------------
// grid (37, Bn) x 256 = 296 blocks = 2 per SM (reg-cap occupancy)
__global__ void __launch_bounds__(256) k_emb1(const float* __restrict__ pred,
                       const int* __restrict__ inst,
                       const float* __restrict__ tm){
    __shared__ float sS[8][80];
    int b = blockIdx.y;
    int t = threadIdx.x;
    int lane = t & 31, wid = t >> 5;
    float cnt[NL], a0[NL], a1[NL], a2[NL], a3[NL];
    #pragma unroll
    for (int l=0;l<NL;l++){ cnt[l]=0.f; a0[l]=0.f; a1[l]=0.f; a2[l]=0.f; a3[l]=0.f; }

    const float4* tm4 = (const float4*)(tm + b*HW);
    const int4*   in4 = (const int4*)(inst + b*HW);
    const float4* e0 = (const float4*)(pred + (b*NCH + 6)*HW);
    const float4* e1 = (const float4*)(pred + (b*NCH + 7)*HW);
    const float4* e2 = (const float4*)(pred + (b*NCH + 8)*HW);
    const float4* e3 = (const float4*)(pred + (b*NCH + 9)*HW);
    int stride = gridDim.x*blockDim.x;
    for (int i = blockIdx.x*blockDim.x + t; i < HW4; i += stride){
        float4 m = tm4[i]; int4 gi = in4[i];
        float4 va = e0[i], vb = e1[i], vc = e2[i], vd = e3[i];
        float mv[4] = {m.x, m.y, m.z, m.w};
        int   lv[4] = {gi.x & 15, gi.y & 15, gi.z & 15, gi.w & 15};
        float av[4] = {va.x, va.y, va.z, va.w};
        float bv[4] = {vb.x, vb.y, vb.z, vb.w};
        float cv[4] = {vc.x, vc.y, vc.z, vc.w};
        float dv[4] = {vd.x, vd.y, vd.z, vd.w};
        #pragma unroll
        for (int comp=0; comp<4; comp++){
            bool on = mv[comp] > 0.5f;
            int lab = lv[comp];
            #pragma unroll
            for (int l=0;l<NL;l++){
                bool hit = on && (lab == l);
                if (hit){
                    cnt[l] += 1.f;
                    a0[l] += av[comp];
                    a1[l] += bv[comp];
                    a2[l] += cv[comp];
                    a3[l] += dv[comp];
                }
            }
        }
    }
    #pragma unroll
    for (int l=0;l<NL;l++){
        float v0=cnt[l], v1=a0[l], v2=a1[l], v3=a2[l], v4=a3[l];
        #pragma unroll
        for (int o=16;o;o>>=1){
            v0 += __shfl_down_sync(0xffffffffu, v0, o);
            v1 += __shfl_down_sync(0xffffffffu, v1, o);
            v2 += __shfl_down_sync(0xffffffffu, v2, o);
            v3 += __shfl_down_sync(0xffffffffu, v3, o);
            v4 += __shfl_down_sync(0xffffffffu, v4, o);
        }
        if (lane == 0){
            sS[wid][l*5+0]=v0; sS[wid][l*5+1]=v1; sS[wid][l*5+2]=v2;
            sS[wid][l*5+3]=v3; sS[wid][l*5+4]=v4;
        }
    }
    __syncthreads();
    if (t < 80){
        float s = 0.f;
        #pragma unroll
        for (int w=0;w<8;w++) s += sS[w][t];
        if (s != 0.f){
            int l = t/5, comp = t - 5*l;
            if (comp == 0) atomicAdd(&gS.embCnt[b][l], s);
            else           atomicAdd(&gS.embSum[b][l][comp-1], s);
        }
    }
}

// ------- FUSED emb2 (hinge variance) + kernels dice; flat grid 3200x256 ----
__global__ void __launch_bounds__(256) k_emb2kern(const float* __restrict__ pred,
                           const int* __restrict__ inst,
                           const float* __restrict__ gtk,
                           const float* __restrict__ tm){
    __shared__ float sM[NL][4];
    __shared__ float sInv[NL];
    __shared__ float sRedL[8];
    __shared__ float sRedK[8][15];
    int b = blockIdx.x / 400;
    int i = (blockIdx.x - b*400)*256 + threadIdx.x;
    if (threadIdx.x < NL){
        int l = threadIdx.x;
        float c = gS.embCnt[b][l];
        float inv = 1.f / fmaxf(c, 1.f);
        sInv[l] = inv;
        #pragma unroll
        for (int d=0;d<4;d++) sM[l][d] = gS.embSum[b][l][d]*inv;
    }
    __syncthreads();
    float4 m = ((const float4*)(tm + b*HW))[i];
    int4 gi  = ((const int4*)(inst + b*HW))[i];
    float4 a = ((const float4*)(pred + (b*NCH + 6)*HW))[i];
    float4 bb= ((const float4*)(pred + (b*NCH + 7)*HW))[i];
    float4 c = ((const float4*)(pred + (b*NCH + 8)*HW))[i];
    float4 d = ((const float4*)(pred + (b*NCH + 9)*HW))[i];
    const float* pb = pred + (b*NCH + 1)*HW;
    const float* gb = gtk  + b*NKER*HW;

    float mv[4] = {m.x, m.y, m.z, m.w};
    int   lv[4] = {gi.x & 15, gi.y & 15, gi.z & 15, gi.w & 15};
    float av[4] = {a.x, a.y, a.z, a.w};
    float bv[4] = {bb.x, bb.y, bb.z, bb.w};
    float cv[4] = {c.x, c.y, c.z, c.w};
    float dv[4] = {d.x, d.y, d.z, d.w};

    float si[5], s1[5], s2[5];
    #pragma unroll
    for (int kc=0;kc<5;kc++){
        float4 p = ((const float4*)(pb + kc*HW))[i];
        float4 g = ((const float4*)(gb + kc*HW))[i];
        float ai=0.f,u=0.f,cc=0.f;
        if (mv[0] > 0.5f){ float pp = sigm(p.x); ai+=pp*g.x; u+=pp*pp; cc+=g.x; }
        if (mv[1] > 0.5f){ float pp = sigm(p.y); ai+=pp*g.y; u+=pp*pp; cc+=g.y; }
        if (mv[2] > 0.5f){ float pp = sigm(p.z); ai+=pp*g.z; u+=pp*pp; cc+=g.z; }
        if (mv[3] > 0.5f){ float pp = sigm(p.w); ai+=pp*g.w; u+=pp*pp; cc+=g.w; }
        si[kc]=ai; s1[kc]=u; s2[kc]=cc;
    }

    float acc = 0.f;
    #pragma unroll
    for (int comp=0; comp<4; comp++){
        if (mv[comp] > 0.5f){
            int l = lv[comp];
            float v0 = av[comp] - sM[l][0];
            float v1 = bv[comp] - sM[l][1];
            float v2 = cv[comp] - sM[l][2];
            float v3 = dv[comp] - sM[l][3];
            float dd = sqrtf(v0*v0+v1*v1+v2*v2+v3*v3 + 1e-12f);
            float h = dd - 0.5f;
            if (h > 0.f) acc += h*h*sInv[l];
        }
    }

    int lane = threadIdx.x & 31, wid = threadIdx.x >> 5;
    #pragma unroll
    for (int o=16;o;o>>=1) acc += __shfl_down_sync(0xffffffffu, acc, o);
    if (lane == 0) sRedL[wid] = acc;
    #pragma unroll
    for (int kc=0;kc<5;kc++){
        float ai = si[kc], u = s1[kc], cc = s2[kc];
        #pragma unroll
        for (int o=16;o;o>>=1){
            ai += __shfl_down_sync(0xffffffffu, ai, o);
            u  += __shfl_down_sync(0xffffffffu, u, o);
            cc += __shfl_down_sync(0xffffffffu, cc, o);
        }
        if (lane == 0){ sRedK[wid][kc*3]=ai; sRedK[wid][kc*3+1]=u; sRedK[wid][kc*3+2]=cc; }
    }
    __syncthreads();
    if (threadIdx.x == 0){
        float s = 0.f;
        #pragma unroll
        for (int w=0;w<8;w++) s += sRedL[w];
        if (s != 0.f) atomicAdd(&gS.lvSum[b], s);
    }
    if (threadIdx.x >= 32 && threadIdx.x < 47){
        int j = threadIdx.x - 32;
        float s = 0.f;
        #pragma unroll
        for (int w=0;w<8;w++) s += sRedK[w][j];
        int kc = j/3, comp = j - 3*kc;
        if (s != 0.f){
            if (comp==0) atomicAdd(&gS.kInter[b*NKER+kc], s);
            else if (comp==1) atomicAdd(&gS.kU1[b*NKER+kc], s);
            else atomicAdd(&gS.kU2[b*NKER+kc], s);
        }
    }
}

// ------- FUSED select + FULLY PARALLEL final; 1 block x 1024 ---------------
__global__ void __launch_bounds__(1024, 1) k_selfinal(float* out){
    __shared__ Scal sG;                    // parallel-staged copy of gS
    __shared__ unsigned hC[4096];
    __shared__ float    hQ[4096];
    __shared__ unsigned scC[1024];
    __shared__ float    scQ[1024];
    __shared__ float    sNegselArr[Bn];
    __shared__ int      sRare[Bn];
    __shared__ int      sAnyRare;
    __shared__ unsigned sPrefix;
    __shared__ int      sK;
    __shared__ float    sAcc;
    __shared__ float sMean[Bn][NL][4];
    __shared__ float sPres[Bn][NL];
    __shared__ float sN[Bn];
    __shared__ float sLd[Bn];
    __shared__ float sLr[Bn];
    __shared__ float sLossT, sLossK, sLvT, sLdT, sLrT;
    int t = threadIdx.x;

    // stage gS -> shared in one coalesced sweep
    for (int i = t; i < (int)SCAL_WORDS; i += 1024)
        ((unsigned*)&sG)[i] = ((const unsigned*)&gS)[i];
    if (t == 0){ sAnyRare = 0; sLossT=0.f; sLossK=0.f; sLvT=0.f; sLdT=0.f; sLrT=0.f; }
    __syncthreads();

    // ---- OHEM: parallel common-path check ----
    if (t < Bn){
        int b = t;
        int cnt = sG.negcount[b];
        int k0 = 3*sG.npos[b]; if (k0 > cnt) k0 = cnt;
        int rare = 0;
        if (k0 >= cnt) sNegselArr[b] = sG.totNegQ[b];
        else if (k0 <= 0) sNegselArr[b] = 0.f;
        else { rare = 1; atomicExch(&sAnyRare, 1); }
        sRare[b] = rare;
    }
    __syncthreads();
    if (sAnyRare){
        for (int b=0;b<Bn;b++){
            if (!sRare[b]) continue;
            int cnt = sG.negcount[b];
            int k0 = 3*sG.npos[b]; if (k0 > cnt) k0 = cnt;
            if (t == 0){ sK = k0; sAcc = 0.f; sPrefix = 0u; }
            __syncthreads();
            const unsigned* nb = g_negbits + b*HW;
            for (int level = 1; level <= 3; level++){
                int K = sK;
                unsigned pfx = sPrefix;
                for (int i=t;i<4096;i+=1024){ hC[i]=0u; hQ[i]=0.f; }
                __syncthreads();
                for (int j = t; j - t < cnt; j += 1024){
                    bool in = j < cnt;
                    unsigned bits = in ? nb[j] : 0u;
                    unsigned bin = 0; bool ok = false;
                    if (in){
                        if (level == 1){ bin = bits >> 20; ok = true; }
                        else if (level == 2){ ok = (bits>>20)==(pfx>>20); bin = (bits>>8)&0xFFFu; }
                        else { ok = (bits>>8)==(pfx>>8); bin = bits & 0xFFu; }
                    }
                    float v = __uint_as_float(bits);
                    float q = v*v;
                    unsigned key = ok ? bin : 0xFFFFFFFFu;
                    unsigned grp = __match_any_sync(0xffffffffu, key);
                    if (grp == 0xffffffffu){
                        if (ok){
                            #pragma unroll
                            for (int o=16;o;o>>=1) q += __shfl_down_sync(0xffffffffu, q, o);
                            if ((t & 31) == 0){ atomicAdd(&hC[bin], 32u); atomicAdd(&hQ[bin], q); }
                        }
                    } else if (ok){
                        atomicAdd(&hC[bin], 1u); atomicAdd(&hQ[bin], q);
                    }
                }
                __syncthreads();
                int nbins = (level == 3) ? 256 : 4096;
                int per = (nbins >= 1024) ? (nbins >> 10) : 1;
                int hi = nbins - 1 - t*per;
                unsigned c = 0; float q = 0.f;
                if (hi >= 0){
                    for (int i=0;i<per;i++){ int bx = hi - i; if (bx >= 0){ c += hC[bx]; q += hQ[bx]; } }
                }
                scC[t] = c; scQ[t] = q;
                __syncthreads();
                for (int off=1; off<1024; off<<=1){
                    unsigned cv = (t >= off) ? scC[t-off] : 0u;
                    float    qv = (t >= off) ? scQ[t-off] : 0.f;
                    __syncthreads();
                    scC[t] += cv; scQ[t] += qv;
                    __syncthreads();
                }
                unsigned incl = scC[t], excl = incl - c;
                if (hi >= 0 && (int)excl < K && K <= (int)incl){
                    unsigned acc = excl;
                    float qacc = scQ[t] - q;
                    int chosen = hi;
                    for (int i=0;i<per;i++){
                        int bx = hi - i;
                        unsigned cc = hC[bx];
                        if (acc + cc >= (unsigned)K){ chosen = bx; break; }
                        acc += cc; qacc += hQ[bx];
                    }
                    sK = K - (int)acc;
                    sAcc += qacc;
                    if (level == 1)      sPrefix = ((unsigned)chosen) << 20;
                    else if (level == 2) sPrefix |= ((unsigned)chosen) << 8;
                    else                 sPrefix |= (unsigned)chosen;
                }
                __syncthreads();
            }
            if (t == 0){
                float tv = __uint_as_float(sPrefix);
                sNegselArr[b] = sAcc + (float)sK * tv * tv;
            }
            __syncthreads();
        }
    }

    // ---- parallel final assembly (all reads from shared) ----
    if (t < Bn){ sN[t]=0.f; sLd[t]=0.f; sLr[t]=0.f; }
    __syncthreads();
    if (t < Bn*NL){                     // 128 threads: means + presence
        int b = t >> 4, l = t & 15;
        float cc = sG.embCnt[b][l];
        float pres = (cc > 0.f) ? 1.f : 0.f;
        sPres[b][l] = pres;
        float inv = 1.f/fmaxf(cc,1.f);
        #pragma unroll
        for (int d=0;d<4;d++) sMean[b][l][d] = sG.embSum[b][l][d]*inv;
        if (pres != 0.f) atomicAdd(&sN[b], 1.f);
    }
    __syncthreads();
    if (t < Bn*NL){                     // lr terms
        int b = t >> 4, l = t & 15;
        if (sPres[b][l] != 0.f){
            float d2=0.f;
            #pragma unroll
            for (int d=0;d<4;d++) d2 += sMean[b][l][d]*sMean[b][l][d];
            atomicAdd(&sLr[b], sqrtf(d2 + 1e-12f));
        }
    }
    if (t < Bn*120){                    // 960 threads: ld pair terms
        int b = t / 120, p = t - b*120;
        int ii = 0, rem = p;
        #pragma unroll
        for (int k=0;k<15;k++){
            int row = 15 - k;
            if (rem < row){ ii = k; break; }
            rem -= row;
        }
        int jj = ii + 1 + rem;
        if (sPres[b][ii] != 0.f && sPres[b][jj] != 0.f){
            float d2=0.f;
            #pragma unroll
            for (int d=0;d<4;d++){
                float df = sMean[b][ii][d]-sMean[b][jj][d];
                d2 += df*df;
            }
            float pd = sqrtf(d2 + 1e-12f);
            float h = fmaxf(3.0f - pd, 0.f);
            if (h > 0.f) atomicAdd(&sLd[b], h*h);
        }
    }
    // dice terms in parallel (needs sNegselArr -> after the sync below)
    __syncthreads();
    if (t < Bn){                        // text dice per batch
        int b = t;
        float inter = sG.posSum[b];
        float uni = sG.posSum2[b] + sNegselArr[b] + (float)sG.npos[b] + 1e-6f;
        atomicAdd(&sLossT, 1.f - 2.f*inter/uni);
    }
    if (t >= 32 && t < 32 + Bn*NKER){   // kernel dice per row
        int r = t - 32;
        float uni = sG.kU1[r] + sG.kU2[r] + 1e-6f;
        atomicAdd(&sLossK, 1.f - 2.f*sG.kInter[r]/uni);
    }
    __syncthreads();
    if (t < Bn){                        // per-batch emb combine
        int b = t;
        float nf = sN[b];
        float act = (nf > 1.f) ? 1.f : 0.f;
        if (act != 0.f){
            atomicAdd(&sLvT, sG.lvSum[b] / fmaxf(nf, 1.f));
            atomicAdd(&sLdT, sLd[b] / fmaxf(nf*(nf-1.f), 1.f));
            atomicAdd(&sLrT, sLr[b] / fmaxf(nf, 1.f));
        }
    }
    __syncthreads();
    if (t != 0) return;
    float loss_text = sLossT / (float)Bn;
    float loss_k = sLossK / (float)(Bn*NKER);
    float loss_emb = 0.25f*(sLvT + sLdT + 0.001f*(sLrT/(float)Bn));
    float loss = loss_k + 0.5f*loss_text + loss_emb;
    out[0]=loss; out[1]=loss_text; out[2]=loss_k; out[3]=loss_emb;
}

// ---- launch: 5 workloads, emb1-first overlap ------------------------------
extern "C" void kernel_launch(void* const* d_in, const int* in_sizes, int n_in,
                              void* d_out, int out_size){
    const float* pred   = (const float*)d_in[0];
    const float* gtText = (const float*)d_in[1];
    const float* gtk    = (const float*)d_in[2];
    const float* tm     = (const float*)d_in[3];
    const int*   inst   = (const int*)d_in[4];
    float* out = (float*)d_out;

    static cudaStream_t s1 = nullptr, s2 = nullptr;
    static cudaEvent_t ev0 = nullptr, ev1 = nullptr, ev2 = nullptr;
    static void* pS = nullptr;
    if (s1 == nullptr){
        cudaStreamCreateWithFlags(&s1, cudaStreamNonBlocking);
        cudaStreamCreateWithFlags(&s2, cudaStreamNonBlocking);
        cudaEventCreateWithFlags(&ev0, cudaEventDisableTiming);
        cudaEventCreateWithFlags(&ev1, cudaEventDisableTiming);
        cudaEventCreateWithFlags(&ev2, cudaEventDisableTiming);
        cudaGetSymbolAddress(&pS, gS);
    }

    cudaMemsetAsync(pS, 0, sizeof(Scal), 0);             // 1
    cudaEventRecord(ev0, 0);

    // chain A (s2): emb1 -> emb2kern
    cudaStreamWaitEvent(s2, ev0, 0);
    k_emb1<<<dim3(37, Bn), 256, 0, s2>>>(pred, inst, tm);          // 2
    k_emb2kern<<<3200, 256, 0, s2>>>(pred, inst, gtk, tm);         // 3
    cudaEventRecord(ev2, s2);

    // chain B (s1): dilstats
    cudaStreamWaitEvent(s1, ev0, 0);
    k_dilstats<<<dim3(20,20,Bn), dim3(32,8), 0, s1>>>(pred, gtText, tm);  // 4
    cudaEventRecord(ev1, s1);

    // join -> fused select+final
    cudaStreamWaitEvent(0, ev1, 0);
    cudaStreamWaitEvent(0, ev2, 0);
    k_selfinal<<<1, 1024>>>(out);                                  // 5
}

// round 16
// speedup vs baseline: 3.1222x; 1.0930x over previous
#include <cuda_runtime.h>
#include <math.h>

#define Bn 8
#define Hh 640
#define Ww 640
#define HW (Hh*Ww)          // 409600
#define HW4 (HW/4)          // 102400
#define NCH 10
#define NKER 5
#define NL 16
#define NEGINF (-1e30f)

// ---------------- scratch ----------------
struct Scal {
    int   negcount[Bn];
    int   npos[Bn];
    float posSum[Bn], posSum2[Bn], totNegQ[Bn], lvSum[Bn];
    float kInter[Bn*NKER], kU1[Bn*NKER], kU2[Bn*NKER];
    float embCnt[Bn][NL];
    float embSum[Bn][NL][4];
};
#define SCAL_WORDS (sizeof(Scal)/4)
__device__ Scal gS;
__device__ unsigned g_negbits[Bn*HW];

__device__ __forceinline__ float sigm(float x){ return 1.0f/(1.0f+expf(-x)); }

// ------- fused dilate (sigmoid-of-max) + OHEM stats + staged compaction ----
// grid (20,20,Bn), block (32,8). Tile 32x32, halo 4.
__global__ void k_dilstats(const float* __restrict__ pred,
                           const float* __restrict__ gt,
                           const float* __restrict__ tm){
    __shared__ float sIn[40][41];
    __shared__ float sHm[40][33];
    __shared__ unsigned sNeg[1024];
    __shared__ int sCnt, sBase;
    __shared__ float sR0[8], sR1[8], sR2[8], sR3[8];
    int b = blockIdx.z;
    int gx0 = blockIdx.x*32 - 4, gy0 = blockIdx.y*32 - 4;
    int tid = threadIdx.y*32 + threadIdx.x;
    int lane = tid & 31, wid = tid >> 5;
    const float* p0 = pred + b*NCH*HW;

    if (tid == 0) sCnt = 0;
    for (int idx = tid; idx < 1600; idx += 256){
        int r = idx/40, c = idx - 40*r;
        int gy = gy0 + r, gx = gx0 + c;
        sIn[r][c] = (gy>=0 && gy<Hh && gx>=0 && gx<Ww) ? p0[gy*Ww + gx] : NEGINF;
    }
    __syncthreads();
    for (int idx = tid; idx < 1280; idx += 256){
        int r = idx >> 5, c = idx & 31;
        float m = sIn[r][c];
        #pragma unroll
        for (int j=1;j<9;j++) m = fmaxf(m, sIn[r][c+j]);
        sHm[r][c] = m;
    }
    __syncthreads();

    int pc = 0; float ps = 0.f, ps2 = 0.f, qn = 0.f;
    #pragma unroll
    for (int k=0;k<4;k++){
        int r = threadIdx.y*4 + k;
        int c = threadIdx.x;
        float m = sHm[r][c];
        #pragma unroll
        for (int j=1;j<9;j++) m = fmaxf(m, sHm[r+j][c]);
        float v = sigm(m);                  // sigmoid after max (monotone)
        int gy = gy0 + 4 + r, gx = gx0 + 4 + c;
        int gi = b*HW + gy*Ww + gx;
        float g  = gt[gi];
        float mm = tm[gi];
        bool isPos = (g > 0.5f) && (mm > 0.5f);
        bool isNeg = (g <= 0.5f) && (mm > 0.5f);
        if (isPos){ pc++; ps += v; ps2 += v*v; }
        if (isNeg) qn += v*v;
        unsigned ball = __ballot_sync(0xffffffffu, isNeg);
        if (isNeg){
            int rank = __popc(ball & ((1u<<lane)-1u));
            int leader = __ffs(ball)-1;
            int base = 0;
            if (lane == leader) base = atomicAdd(&sCnt, __popc(ball));
            base = __shfl_sync(ball, base, leader);
            sNeg[base + rank] = __float_as_uint(v);
        }
    }
    #pragma unroll
    for (int o=16;o;o>>=1){
        pc  += __shfl_down_sync(0xffffffffu, pc, o);
        ps  += __shfl_down_sync(0xffffffffu, ps, o);
        ps2 += __shfl_down_sync(0xffffffffu, ps2, o);
        qn  += __shfl_down_sync(0xffffffffu, qn, o);
    }
    if (lane == 0){ sR0[wid]=(float)pc; sR1[wid]=ps; sR2[wid]=ps2; sR3[wid]=qn; }
    __syncthreads();        // covers sNeg, sCnt, sR*
    if (tid == 0){
        float a=0,bb=0,cc=0,dd=0;
        #pragma unroll
        for (int w=0;w<8;w++){ a+=sR0[w]; bb+=sR1[w]; cc+=sR2[w]; dd+=sR3[w]; }
        if (a  != 0.f) atomicAdd(&gS.npos[b], (int)a);
        if (bb != 0.f) atomicAdd(&gS.posSum[b], bb);
        if (cc != 0.f) atomicAdd(&gS.posSum2[b], cc);
        if (dd != 0.f) atomicAdd(&gS.totNegQ[b], dd);
        sBase = atomicAdd(&gS.negcount[b], sCnt);
    }
    __syncthreads();
    int cnt = sCnt, base = sBase;
    unsigned* dst = g_negbits + b*HW + base;
    for (int i = tid; i < cnt; i += 256) dst[i] = sNeg[i];
}

// ------- emb pass 1: REGISTER accumulators + predicated adds ---------------
// grid (37, Bn) x 256 = 296 blocks = 2 per SM
__global__ void __launch_bounds__(256) k_emb1(const float* __restrict__ pred,
                       const int* __restrict__ inst,
                       const float* __restrict__ tm){
    __shared__ float sS[8][80];
    int b = blockIdx.y;
    int t = threadIdx.x;
    int lane = t & 31, wid = t >> 5;
    float cnt[NL], a0[NL], a1[NL], a2[NL], a3[NL];
    #pragma unroll
    for (int l=0;l<NL;l++){ cnt[l]=0.f; a0[l]=0.f; a1[l]=0.f; a2[l]=0.f; a3[l]=0.f; }

    const float4* tm4 = (const float4*)(tm + b*HW);
    const int4*   in4 = (const int4*)(inst + b*HW);
    const float4* e0 = (const float4*)(pred + (b*NCH + 6)*HW);
    const float4* e1 = (const float4*)(pred + (b*NCH + 7)*HW);
    const float4* e2 = (const float4*)(pred + (b*NCH + 8)*HW);
    const float4* e3 = (const float4*)(pred + (b*NCH + 9)*HW);
    int stride = gridDim.x*blockDim.x;
    for (int i = blockIdx.x*blockDim.x + t; i < HW4; i += stride){
        float4 m = tm4[i]; int4 gi = in4[i];
        float4 va = e0[i], vb = e1[i], vc = e2[i], vd = e3[i];
        float mv[4] = {m.x, m.y, m.z, m.w};
        int   lv[4] = {gi.x & 15, gi.y & 15, gi.z & 15, gi.w & 15};
        float av[4] = {va.x, va.y, va.z, va.w};
        float bv[4] = {vb.x, vb.y, vb.z, vb.w};
        float cv[4] = {vc.x, vc.y, vc.z, vc.w};
        float dv[4] = {vd.x, vd.y, vd.z, vd.w};
        #pragma unroll
        for (int comp=0; comp<4; comp++){
            bool on = mv[comp] > 0.5f;
            int lab = lv[comp];
            #pragma unroll
            for (int l=0;l<NL;l++){
                bool hit = on && (lab == l);
                if (hit){
                    cnt[l] += 1.f;
                    a0[l] += av[comp];
                    a1[l] += bv[comp];
                    a2[l] += cv[comp];
                    a3[l] += dv[comp];
                }
            }
        }
    }
    #pragma unroll
    for (int l=0;l<NL;l++){
        float v0=cnt[l], v1=a0[l], v2=a1[l], v3=a2[l], v4=a3[l];
        #pragma unroll
        for (int o=16;o;o>>=1){
            v0 += __shfl_down_sync(0xffffffffu, v0, o);
            v1 += __shfl_down_sync(0xffffffffu, v1, o);
            v2 += __shfl_down_sync(0xffffffffu, v2, o);
            v3 += __shfl_down_sync(0xffffffffu, v3, o);
            v4 += __shfl_down_sync(0xffffffffu, v4, o);
        }
        if (lane == 0){
            sS[wid][l*5+0]=v0; sS[wid][l*5+1]=v1; sS[wid][l*5+2]=v2;
            sS[wid][l*5+3]=v3; sS[wid][l*5+4]=v4;
        }
    }
    __syncthreads();
    if (t < 80){
        float s = 0.f;
        #pragma unroll
        for (int w=0;w<8;w++) s += sS[w][t];
        if (s != 0.f){
            int l = t/5, comp = t - 5*l;
            if (comp == 0) atomicAdd(&gS.embCnt[b][l], s);
            else           atomicAdd(&gS.embSum[b][l][comp-1], s);
        }
    }
}

// ---------------- kernels dice: flat grid, 1 quad/thread (independent) -----
// grid 3200 x 256
__global__ void __launch_bounds__(256) k_kern(const float* __restrict__ pred,
                       const float* __restrict__ gtk,
                       const float* __restrict__ tm){
    __shared__ float sRed[8][15];
    int b = blockIdx.x / 400;
    int i = (blockIdx.x - b*400)*256 + threadIdx.x;
    float4 m = ((const float4*)(tm + b*HW))[i];
    const float* pb = pred + (b*NCH + 1)*HW;
    const float* gb = gtk  + b*NKER*HW;
    float si[5], s1[5], s2[5];
    #pragma unroll
    for (int kc=0;kc<5;kc++){
        float4 p = ((const float4*)(pb + kc*HW))[i];
        float4 g = ((const float4*)(gb + kc*HW))[i];
        float a=0.f,u=0.f,c=0.f;
        if (m.x > 0.5f){ float pp = sigm(p.x); a+=pp*g.x; u+=pp*pp; c+=g.x; }
        if (m.y > 0.5f){ float pp = sigm(p.y); a+=pp*g.y; u+=pp*pp; c+=g.y; }
        if (m.z > 0.5f){ float pp = sigm(p.z); a+=pp*g.z; u+=pp*pp; c+=g.z; }
        if (m.w > 0.5f){ float pp = sigm(p.w); a+=pp*g.w; u+=pp*pp; c+=g.w; }
        si[kc]=a; s1[kc]=u; s2[kc]=c;
    }
    int lane = threadIdx.x & 31, wid = threadIdx.x >> 5;
    #pragma unroll
    for (int kc=0;kc<5;kc++){
        float a = si[kc], u = s1[kc], c = s2[kc];
        #pragma unroll
        for (int o=16;o;o>>=1){
            a += __shfl_down_sync(0xffffffffu, a, o);
            u += __shfl_down_sync(0xffffffffu, u, o);
            c += __shfl_down_sync(0xffffffffu, c, o);
        }
        if (lane == 0){ sRed[wid][kc*3]=a; sRed[wid][kc*3+1]=u; sRed[wid][kc*3+2]=c; }
    }
    __syncthreads();
    if (threadIdx.x < 15){
        float s = 0.f;
        #pragma unroll
        for (int w=0;w<8;w++) s += sRed[w][threadIdx.x];
        int kc = threadIdx.x/3, comp = threadIdx.x - 3*kc;
        if (s != 0.f){
            if (comp==0) atomicAdd(&gS.kInter[b*NKER+kc], s);
            else if (comp==1) atomicAdd(&gS.kU1[b*NKER+kc], s);
            else atomicAdd(&gS.kU2[b*NKER+kc], s);
        }
    }
}

// ---------------- emb pass 2: hinge variance, flat grid 3200x256 -----------
__global__ void __launch_bounds__(256) k_emb2(const float* __restrict__ pred,
                       const int* __restrict__ inst,
                       const float* __restrict__ tm){
    __shared__ float sM[NL][4];
    __shared__ float sInv[NL];
    __shared__ float sRed[8];
    int b = blockIdx.x / 400;
    int i = (blockIdx.x - b*400)*256 + threadIdx.x;
    if (threadIdx.x < NL){
        int l = threadIdx.x;
        float c = gS.embCnt[b][l];
        float inv = 1.f / fmaxf(c, 1.f);
        sInv[l] = inv;
        #pragma unroll
        for (int d=0;d<4;d++) sM[l][d] = gS.embSum[b][l][d]*inv;
    }
    __syncthreads();
    float4 m = ((const float4*)(tm + b*HW))[i];
    int4 gi  = ((const int4*)(inst + b*HW))[i];
    float4 a = ((const float4*)(pred + (b*NCH + 6)*HW))[i];
    float4 bb= ((const float4*)(pred + (b*NCH + 7)*HW))[i];
    float4 c = ((const float4*)(pred + (b*NCH + 8)*HW))[i];
    float4 d = ((const float4*)(pred + (b*NCH + 9)*HW))[i];
    float acc = 0.f;
    float mv[4] = {m.x, m.y, m.z, m.w};
    int   lv[4] = {gi.x & 15, gi.y & 15, gi.z & 15, gi.w & 15};
    float av[4] = {a.x, a.y, a.z, a.w};
    float bv[4] = {bb.x, bb.y, bb.z, bb.w};
    float cv[4] = {c.x, c.y, c.z, c.w};
    float dv[4] = {d.x, d.y, d.z, d.w};
    #pragma unroll
    for (int comp=0; comp<4; comp++){
        if (mv[comp] > 0.5f){
            int l = lv[comp];
            float v0 = av[comp] - sM[l][0];
            float v1 = bv[comp] - sM[l][1];
            float v2 = cv[comp] - sM[l][2];
            float v3 = dv[comp] - sM[l][3];
            float dd = sqrtf(v0*v0+v1*v1+v2*v2+v3*v3 + 1e-12f);
            float h = dd - 0.5f;
            if (h > 0.f) acc += h*h*sInv[l];
        }
    }
    int lane = threadIdx.x & 31, wid = threadIdx.x >> 5;
    #pragma unroll
    for (int o=16;o;o>>=1) acc += __shfl_down_sync(0xffffffffu, acc, o);
    if (lane == 0) sRed[wid] = acc;
    __syncthreads();
    if (threadIdx.x == 0){
        float s = 0.f;
        #pragma unroll
        for (int w=0;w<8;w++) s += sRed[w];
        if (s != 0.f) atomicAdd(&gS.lvSum[b], s);
    }
}

// ------- FUSED select + FULLY PARALLEL final; 1 block x 1024 ---------------
__global__ void __launch_bounds__(1024, 1) k_selfinal(float* out){
    __shared__ Scal sG;
    __shared__ unsigned hC[4096];
    __shared__ float    hQ[4096];
    __shared__ unsigned scC[1024];
    __shared__ float    scQ[1024];
    __shared__ float    sNegselArr[Bn];
    __shared__ int      sRare[Bn];
    __shared__ int      sAnyRare;
    __shared__ unsigned sPrefix;
    __shared__ int      sK;
    __shared__ float    sAcc;
    __shared__ float sMean[Bn][NL][4];
    __shared__ float sPres[Bn][NL];
    __shared__ float sN[Bn];
    __shared__ float sLd[Bn];
    __shared__ float sLr[Bn];
    __shared__ float sLossT, sLossK, sLvT, sLdT, sLrT;
    int t = threadIdx.x;

    for (int i = t; i < (int)SCAL_WORDS; i += 1024)
        ((unsigned*)&sG)[i] = ((const unsigned*)&gS)[i];
    if (t == 0){ sAnyRare = 0; sLossT=0.f; sLossK=0.f; sLvT=0.f; sLdT=0.f; sLrT=0.f; }
    __syncthreads();

    if (t < Bn){
        int b = t;
        int cnt = sG.negcount[b];
        int k0 = 3*sG.npos[b]; if (k0 > cnt) k0 = cnt;
        int rare = 0;
        if (k0 >= cnt) sNegselArr[b] = sG.totNegQ[b];
        else if (k0 <= 0) sNegselArr[b] = 0.f;
        else { rare = 1; atomicExch(&sAnyRare, 1); }
        sRare[b] = rare;
    }
    __syncthreads();
    if (sAnyRare){
        for (int b=0;b<Bn;b++){
            if (!sRare[b]) continue;
            int cnt = sG.negcount[b];
            int k0 = 3*sG.npos[b]; if (k0 > cnt) k0 = cnt;
            if (t == 0){ sK = k0; sAcc = 0.f; sPrefix = 0u; }
            __syncthreads();
            const unsigned* nb = g_negbits + b*HW;
            for (int level = 1; level <= 3; level++){
                int K = sK;
                unsigned pfx = sPrefix;
                for (int i=t;i<4096;i+=1024){ hC[i]=0u; hQ[i]=0.f; }
                __syncthreads();
                for (int j = t; j - t < cnt; j += 1024){
                    bool in = j < cnt;
                    unsigned bits = in ? nb[j] : 0u;
                    unsigned bin = 0; bool ok = false;
                    if (in){
                        if (level == 1){ bin = bits >> 20; ok = true; }
                        else if (level == 2){ ok = (bits>>20)==(pfx>>20); bin = (bits>>8)&0xFFFu; }
                        else { ok = (bits>>8)==(pfx>>8); bin = bits & 0xFFu; }
                    }
                    float v = __uint_as_float(bits);
                    float q = v*v;
                    unsigned key = ok ? bin : 0xFFFFFFFFu;
                    unsigned grp = __match_any_sync(0xffffffffu, key);
                    if (grp == 0xffffffffu){
                        if (ok){
                            #pragma unroll
                            for (int o=16;o;o>>=1) q += __shfl_down_sync(0xffffffffu, q, o);
                            if ((t & 31) == 0){ atomicAdd(&hC[bin], 32u); atomicAdd(&hQ[bin], q); }
                        }
                    } else if (ok){
                        atomicAdd(&hC[bin], 1u); atomicAdd(&hQ[bin], q);
                    }
                }
                __syncthreads();
                int nbins = (level == 3) ? 256 : 4096;
                int per = (nbins >= 1024) ? (nbins >> 10) : 1;
                int hi = nbins - 1 - t*per;
                unsigned c = 0; float q = 0.f;
                if (hi >= 0){
                    for (int i=0;i<per;i++){ int bx = hi - i; if (bx >= 0){ c += hC[bx]; q += hQ[bx]; } }
                }
                scC[t] = c; scQ[t] = q;
                __syncthreads();
                for (int off=1; off<1024; off<<=1){
                    unsigned cv = (t >= off) ? scC[t-off] : 0u;
                    float    qv = (t >= off) ? scQ[t-off] : 0.f;
                    __syncthreads();
                    scC[t] += cv; scQ[t] += qv;
                    __syncthreads();
                }
                unsigned incl = scC[t], excl = incl - c;
                if (hi >= 0 && (int)excl < K && K <= (int)incl){
                    unsigned acc = excl;
                    float qacc = scQ[t] - q;
                    int chosen = hi;
                    for (int i=0;i<per;i++){
                        int bx = hi - i;
                        unsigned cc = hC[bx];
                        if (acc + cc >= (unsigned)K){ chosen = bx; break; }
                        acc += cc; qacc += hQ[bx];
                    }
                    sK = K - (int)acc;
                    sAcc += qacc;
                    if (level == 1)      sPrefix = ((unsigned)chosen) << 20;
                    else if (level == 2) sPrefix |= ((unsigned)chosen) << 8;
                    else                 sPrefix |= (unsigned)chosen;
                }
                __syncthreads();
            }
            if (t == 0){
                float tv = __uint_as_float(sPrefix);
                sNegselArr[b] = sAcc + (float)sK * tv * tv;
            }
            __syncthreads();
        }
    }

    if (t < Bn){ sN[t]=0.f; sLd[t]=0.f; sLr[t]=0.f; }
    __syncthreads();
    if (t < Bn*NL){
        int b = t >> 4, l = t & 15;
        float cc = sG.embCnt[b][l];
        float pres = (cc > 0.f) ? 1.f : 0.f;
        sPres[b][l] = pres;
        float inv = 1.f/fmaxf(cc,1.f);
        #pragma unroll
        for (int d=0;d<4;d++) sMean[b][l][d] = sG.embSum[b][l][d]*inv;
        if (pres != 0.f) atomicAdd(&sN[b], 1.f);
    }
    __syncthreads();
    if (t < Bn*NL){
        int b = t >> 4, l = t & 15;
        if (sPres[b][l] != 0.f){
            float d2=0.f;
            #pragma unroll
            for (int d=0;d<4;d++) d2 += sMean[b][l][d]*sMean[b][l][d];
            atomicAdd(&sLr[b], sqrtf(d2 + 1e-12f));
        }
    }
    if (t < Bn*120){
        int b = t / 120, p = t - b*120;
        int ii = 0, rem = p;
        #pragma unroll
        for (int k=0;k<15;k++){
            int row = 15 - k;
            if (rem < row){ ii = k; break; }
            rem -= row;
        }
        int jj = ii + 1 + rem;
        if (sPres[b][ii] != 0.f && sPres[b][jj] != 0.f){
            float d2=0.f;
            #pragma unroll
            for (int d=0;d<4;d++){
                float df = sMean[b][ii][d]-sMean[b][jj][d];
                d2 += df*df;
            }
            float pd = sqrtf(d2 + 1e-12f);
            float h = fmaxf(3.0f - pd, 0.f);
            if (h > 0.f) atomicAdd(&sLd[b], h*h);
        }
    }
    __syncthreads();
    if (t < Bn){
        int b = t;
        float inter = sG.posSum[b];
        float uni = sG.posSum2[b] + sNegselArr[b] + (float)sG.npos[b] + 1e-6f;
        atomicAdd(&sLossT, 1.f - 2.f*inter/uni);
    }
    if (t >= 32 && t < 32 + Bn*NKER){
        int r = t - 32;
        float uni = sG.kU1[r] + sG.kU2[r] + 1e-6f;
        atomicAdd(&sLossK, 1.f - 2.f*sG.kInter[r]/uni);
    }
    __syncthreads();
    if (t < Bn){
        int b = t;
        float nf = sN[b];
        float act = (nf > 1.f) ? 1.f : 0.f;
        if (act != 0.f){
            atomicAdd(&sLvT, sG.lvSum[b] / fmaxf(nf, 1.f));
            atomicAdd(&sLdT, sLd[b] / fmaxf(nf*(nf-1.f), 1.f));
            atomicAdd(&sLrT, sLr[b] / fmaxf(nf, 1.f));
        }
    }
    __syncthreads();
    if (t != 0) return;
    float loss_text = sLossT / (float)Bn;
    float loss_k = sLossK / (float)(Bn*NKER);
    float loss_emb = 0.25f*(sLvT + sLdT + 0.001f*(sLrT/(float)Bn));
    float loss = loss_k + 0.5f*loss_text + loss_emb;
    out[0]=loss; out[1]=loss_text; out[2]=loss_k; out[3]=loss_emb;
}

// ---- launch: 3 concurrent chains; kern no longer behind emb1 --------------
extern "C" void kernel_launch(void* const* d_in, const int* in_sizes, int n_in,
                              void* d_out, int out_size){
    const float* pred   = (const float*)d_in[0];
    const float* gtText = (const float*)d_in[1];
    const float* gtk    = (const float*)d_in[2];
    const float* tm     = (const float*)d_in[3];
    const int*   inst   = (const int*)d_in[4];
    float* out = (float*)d_out;

    static cudaStream_t s1 = nullptr, s2 = nullptr;
    static cudaEvent_t ev0 = nullptr, ev1 = nullptr, ev2 = nullptr;
    static void* pS = nullptr;
    if (s1 == nullptr){
        cudaStreamCreateWithFlags(&s1, cudaStreamNonBlocking);
        cudaStreamCreateWithFlags(&s2, cudaStreamNonBlocking);
        cudaEventCreateWithFlags(&ev0, cudaEventDisableTiming);
        cudaEventCreateWithFlags(&ev1, cudaEventDisableTiming);
        cudaEventCreateWithFlags(&ev2, cudaEventDisableTiming);
        cudaGetSymbolAddress(&pS, gS);
    }

    cudaMemsetAsync(pS, 0, sizeof(Scal), 0);             // workload 1
    cudaEventRecord(ev0, 0);

    // chain A (s2): emb1, then emb2 (issued later so emb2 is capture slot 5)
    cudaStreamWaitEvent(s2, ev0, 0);
    k_emb1<<<dim3(37, Bn), 256, 0, s2>>>(pred, inst, tm);                  // 2

    // chain B (s1): dilstats
    cudaStreamWaitEvent(s1, ev0, 0);
    k_dilstats<<<dim3(20,20,Bn), dim3(32,8), 0, s1>>>(pred, gtText, tm);   // 3
    cudaEventRecord(ev1, s1);

    // chain C (main): kern (independent of emb chain)
    k_kern<<<3200, 256>>>(pred, gtk, tm);                                  // 4

    // chain A continued: emb2 after emb1 (stream order preserved)
    k_emb2<<<3200, 256, 0, s2>>>(pred, inst, tm);                          // 5 (captured)
    cudaEventRecord(ev2, s2);

    // join -> fused select+final
    cudaStreamWaitEvent(0, ev1, 0);
    cudaStreamWaitEvent(0, ev2, 0);
    k_selfinal<<<1, 1024>>>(out);                                          // 6
}